// round 1
// baseline (speedup 1.0000x reference)
#include <cuda_runtime.h>
#include <math.h>

// Problem constants
#define Bc  2
#define Sc  1024
#define Dc  1024
#define Nc  16
#define Hc  64
#define NHc 1024
#define Rc  2048
#define SCALE 0.125f          // 1/sqrt(64)
#define INFV  1000000.0f
#define EPSV  1e-9f

// ---------------- scratch (device globals; module-load allocated) ----------
__device__ float g_q [Bc*Sc*NHc];                 // 8 MB  (query@Wq)*scale
__device__ float g_qw[Bc*Sc*NHc];                 // 8 MB  q + r_w_bias*scale
__device__ float g_qr[Bc*Sc*NHc];                 // 8 MB  q + r_r_bias*scale
__device__ float g_qs[Bc*Sc*NHc];                 // 8 MB  q + r_s_bias*scale
__device__ float g_k [Bc*Sc*NHc];                 // 8 MB
__device__ float g_v [Bc*Sc*NHc];                 // 8 MB
__device__ float g_rh[Rc*NHc];                    // 8 MB  r @ r_kernel
__device__ float g_pos[(long long)Bc*Nc*Sc*Rc];   // 268 MB pos_full [B,N,S,R]
__device__ float g_sc [(long long)Bc*Nc*Sc*Sc];   // 134 MB scores/probs
__device__ float g_ttd[Bc*Sc*Nc*2];               // segment dots (diff,same)
__device__ float g_av [Bc*Sc*NHc];                // 8 MB attn_vec [B,S,N,H]
__device__ float g_ao [Bc*Sc*Dc];                 // 8 MB attn_out

// ---------------- generic tiled SGEMM ---------------------------------------
// C[M,N] = alpha * A[M,K] @ op(B) (+ bias), batched over z = b*nHeads + h.
// op(B) = B[K,N] (NN) or B[N,K]^T (NT). Requires M,N % 64 == 0, K % 16 == 0.
#define BM 64
#define BN 64
#define BK 16

template<bool TRANSB>
__global__ __launch_bounds__(256)
void gemm_k(const float* __restrict__ A, const float* __restrict__ Bm,
            const float* __restrict__ bias, float* __restrict__ C,
            int M, int N, int K, int lda, int ldb, int ldc,
            long long sAb, long long sAn, long long sBb, long long sBn,
            long long sCb, long long sCn, int nHeads, float alpha)
{
    int z = blockIdx.z;
    int b = z / nHeads, h = z - b * nHeads;
    A  += (long long)b * sAb + (long long)h * sAn;
    Bm += (long long)b * sBb + (long long)h * sBn;
    C  += (long long)b * sCb + (long long)h * sCn;

    __shared__ float As[BK][BM];
    __shared__ float Bs[BK][BN];

    const int m0 = blockIdx.y * BM;
    const int n0 = blockIdx.x * BN;
    const int tid = threadIdx.x;
    const int ty = tid >> 4, tx = tid & 15;

    float acc[4][4] = {};

    for (int k0 = 0; k0 < K; k0 += BK) {
        // Load A tile 64x16 -> As[k][m]
        {
            int kk = tid & 15;
            int r  = tid >> 4;
            #pragma unroll
            for (int p = 0; p < 4; ++p)
                As[kk][r + p*16] = A[(long long)(m0 + r + p*16) * lda + k0 + kk];
        }
        // Load B tile -> Bs[k][n]
        if (TRANSB) {
            int kk = tid & 15;
            int j  = tid >> 4;
            #pragma unroll
            for (int p = 0; p < 4; ++p)
                Bs[kk][j + p*16] = Bm[(long long)(n0 + j + p*16) * ldb + k0 + kk];
        } else {
            int j  = tid & 63;
            int kk = tid >> 6;
            #pragma unroll
            for (int p = 0; p < 4; ++p)
                Bs[kk + p*4][j] = Bm[(long long)(k0 + kk + p*4) * ldb + n0 + j];
        }
        __syncthreads();

        #pragma unroll
        for (int kk = 0; kk < BK; ++kk) {
            float a[4], bb[4];
            #pragma unroll
            for (int u = 0; u < 4; ++u) a[u]  = As[kk][ty*4 + u];
            #pragma unroll
            for (int u = 0; u < 4; ++u) bb[u] = Bs[kk][tx*4 + u];
            #pragma unroll
            for (int u = 0; u < 4; ++u)
                #pragma unroll
                for (int w = 0; w < 4; ++w)
                    acc[u][w] += a[u] * bb[w];
        }
        __syncthreads();
    }

    #pragma unroll
    for (int u = 0; u < 4; ++u) {
        int row = m0 + ty*4 + u;
        #pragma unroll
        for (int w = 0; w < 4; ++w) {
            int col = n0 + tx*4 + w;
            float val = alpha * acc[u][w];
            if (bias) val += bias[col];
            C[(long long)row * ldc + col] = val;
        }
    }
}

// ---------------- q variants -------------------------------------------------
__global__ void qvar_k(const float* __restrict__ q,
                       const float* __restrict__ rwb, const float* __restrict__ rrb,
                       const float* __restrict__ rsb,
                       float* __restrict__ qw, float* __restrict__ qr, float* __restrict__ qs)
{
    long long i = (long long)blockIdx.x * 256 + threadIdx.x;
    int nh = (int)(i & (NHc - 1));
    float qv = q[i];
    qw[i] = qv + rwb[nh] * SCALE;
    qr[i] = qv + rrb[nh] * SCALE;
    qs[i] = qv + rsb[nh] * SCALE;
}

// ---------------- segment-embedding dots ------------------------------------
// ttd[(b*S+s)*N+n][0] = qs . seg[0,n,:], [1] = qs . seg[1,n,:]
__global__ void ttdots_k(const float* __restrict__ qs, const float* __restrict__ seg,
                         float* __restrict__ ttd)
{
    int gw   = (blockIdx.x * blockDim.x + threadIdx.x) >> 5;
    int lane = threadIdx.x & 31;
    if (gw >= Bc*Sc*Nc) return;
    int n = gw & (Nc - 1);
    const float* q = qs + (long long)gw * Hc;
    float d0 = 0.f, d1 = 0.f;
    #pragma unroll
    for (int h = lane; h < Hc; h += 32) {
        float qv = q[h];
        d0 += qv * seg[n*Hc + h];
        d1 += qv * seg[(Nc + n)*Hc + h];
    }
    #pragma unroll
    for (int o = 16; o; o >>= 1) {
        d0 += __shfl_down_sync(0xffffffffu, d0, o);
        d1 += __shfl_down_sync(0xffffffffu, d1, o);
    }
    if (lane == 0) { ttd[2*gw] = d0; ttd[2*gw + 1] = d1; }
}

// ---------------- score assembly ---------------------------------------------
// score[b,n,i,j] += pos[b,n,i,1024+j-i]*cls + tt*cls - INF*(1-mask[b,j])
__global__ void combine_k(float* __restrict__ sc, const float* __restrict__ pos,
                          const float* __restrict__ ttd,
                          const unsigned char* __restrict__ ttm,
                          const float* __restrict__ clsm,
                          const int* __restrict__ amask)
{
    long long idx = (long long)blockIdx.x * 256 + threadIdx.x;
    int j  = (int)(idx & (Sc - 1));
    long long r = idx >> 10;
    int i  = (int)(r & (Sc - 1));
    long long bn = r >> 10;              // b*N + n
    int b  = (int)(bn >> 4);
    float pv = pos[(bn * Sc + i) * Rc + (Sc + j - i)];
    const float* td = ttd + (((long long)b * Sc + i) * Nc + (bn & (Nc - 1))) * 2;
    float tt = ttm[((long long)b * Sc + i) * Sc + j] ? td[1] : td[0];
    float cl = clsm[i * Sc + j];
    float m  = (float)amask[b * Sc + j];
    sc[idx] += pv * cl + tt * cl - INFV * (1.0f - m);
}

// ---------------- row softmax (row length 1024) -------------------------------
__global__ void softmax_k(float* __restrict__ sc)
{
    __shared__ float red[256];
    long long row = blockIdx.x;
    float* p = sc + row * (long long)Sc;
    int t = threadIdx.x;
    float v[4];
    float m = -3.4e38f;
    #pragma unroll
    for (int u = 0; u < 4; ++u) { v[u] = p[t + u*256]; m = fmaxf(m, v[u]); }
    red[t] = m; __syncthreads();
    #pragma unroll
    for (int s = 128; s; s >>= 1) { if (t < s) red[t] = fmaxf(red[t], red[t + s]); __syncthreads(); }
    m = red[0]; __syncthreads();
    float sum = 0.f;
    #pragma unroll
    for (int u = 0; u < 4; ++u) { v[u] = expf(v[u] - m); sum += v[u]; }
    red[t] = sum; __syncthreads();
    #pragma unroll
    for (int s = 128; s; s >>= 1) { if (t < s) red[t] += red[t + s]; __syncthreads(); }
    float inv = 1.0f / red[0];
    #pragma unroll
    for (int u = 0; u < 4; ++u) p[t + u*256] = v[u] * inv;
}

// ---------------- residual + LayerNorm ----------------------------------------
__global__ void ln_k(const float* __restrict__ query, const float* __restrict__ ao,
                     const float* __restrict__ gamma, const float* __restrict__ beta,
                     float* __restrict__ out)
{
    __shared__ float red[256];
    long long base = (long long)blockIdx.x * Dc;
    int t = threadIdx.x;
    float x[4]; float s = 0.f;
    #pragma unroll
    for (int u = 0; u < 4; ++u) { x[u] = query[base + t + u*256] + ao[base + t + u*256]; s += x[u]; }
    red[t] = s; __syncthreads();
    #pragma unroll
    for (int o = 128; o; o >>= 1) { if (t < o) red[t] += red[t + o]; __syncthreads(); }
    float mu = red[0] * (1.0f / Dc); __syncthreads();
    float s2 = 0.f;
    #pragma unroll
    for (int u = 0; u < 4; ++u) { float d = x[u] - mu; s2 += d * d; }
    red[t] = s2; __syncthreads();
    #pragma unroll
    for (int o = 128; o; o >>= 1) { if (t < o) red[t] += red[t + o]; __syncthreads(); }
    float inv = rsqrtf(red[0] * (1.0f / Dc) + EPSV);
    #pragma unroll
    for (int u = 0; u < 4; ++u) {
        int c = t + u*256;
        out[base + c] = (x[u] - mu) * inv * gamma[c] + beta[c];
    }
}

// ---------------- driver -------------------------------------------------------
extern "C" void kernel_launch(void* const* d_in, const int* in_sizes, int n_in,
                              void* d_out, int out_size)
{
    const float* query   = (const float*)d_in[0];
    const float* key     = (const float*)d_in[1];
    const float* value   = (const float*)d_in[2];
    const float* r       = (const float*)d_in[3];
    const float* clsm    = (const float*)d_in[4];
    const float* Wq      = (const float*)d_in[5];
    const float* Wk      = (const float*)d_in[6];
    const float* bk      = (const float*)d_in[7];
    const float* Wv      = (const float*)d_in[8];
    const float* bv      = (const float*)d_in[9];
    const float* Wo      = (const float*)d_in[10];
    const float* bo      = (const float*)d_in[11];
    const float* rwb     = (const float*)d_in[12];
    const float* rrb     = (const float*)d_in[13];
    const float* rkern   = (const float*)d_in[14];
    const float* rsb     = (const float*)d_in[15];
    const float* seg     = (const float*)d_in[16];
    const float* gamma   = (const float*)d_in[17];
    const float* beta    = (const float*)d_in[18];
    const unsigned char* ttm = (const unsigned char*)d_in[19];
    const int*   amask   = (const int*)d_in[20];
    float* out = (float*)d_out;

    float *q, *qw, *qr, *qs, *k, *v, *rh, *pos, *sc, *ttd, *av, *ao;
    cudaGetSymbolAddress((void**)&q,   g_q);
    cudaGetSymbolAddress((void**)&qw,  g_qw);
    cudaGetSymbolAddress((void**)&qr,  g_qr);
    cudaGetSymbolAddress((void**)&qs,  g_qs);
    cudaGetSymbolAddress((void**)&k,   g_k);
    cudaGetSymbolAddress((void**)&v,   g_v);
    cudaGetSymbolAddress((void**)&rh,  g_rh);
    cudaGetSymbolAddress((void**)&pos, g_pos);
    cudaGetSymbolAddress((void**)&sc,  g_sc);
    cudaGetSymbolAddress((void**)&ttd, g_ttd);
    cudaGetSymbolAddress((void**)&av,  g_av);
    cudaGetSymbolAddress((void**)&ao,  g_ao);

    const long long SNH = (long long)Sc * NHc;

    // 1) projections: [2048,1024] @ [1024,1024]
    gemm_k<false><<<dim3(NHc/BN, (Bc*Sc)/BM, 1), 256>>>(query, Wq, nullptr, q,
        Bc*Sc, NHc, Dc, Dc, NHc, NHc, 0,0,0,0,0,0, 1, SCALE);
    gemm_k<false><<<dim3(NHc/BN, (Bc*Sc)/BM, 1), 256>>>(key, Wk, bk, k,
        Bc*Sc, NHc, Dc, Dc, NHc, NHc, 0,0,0,0,0,0, 1, 1.0f);
    gemm_k<false><<<dim3(NHc/BN, (Bc*Sc)/BM, 1), 256>>>(value, Wv, bv, v,
        Bc*Sc, NHc, Dc, Dc, NHc, NHc, 0,0,0,0,0,0, 1, 1.0f);
    // r_head: [2048,1024] @ [1024,1024]
    gemm_k<false><<<dim3(NHc/BN, Rc/BM, 1), 256>>>(r, rkern, nullptr, rh,
        Rc, NHc, Dc, Dc, NHc, NHc, 0,0,0,0,0,0, 1, 1.0f);

    // 2) q variants + segment dots
    qvar_k<<<(Bc*Sc*NHc)/256, 256>>>(q, rwb, rrb, rsb, qw, qr, qs);
    ttdots_k<<<(Bc*Sc*Nc*32 + 255)/256, 256>>>(qs, seg, ttd);

    // 3) content = qw . k^T  per (b,n):  [S,H] x [S,H]^T -> [S,S]
    gemm_k<true><<<dim3(Sc/BN, Sc/BM, Bc*Nc), 256>>>(qw, k, nullptr, sc,
        Sc, Sc, Hc, NHc, NHc, Sc,
        SNH, Hc, SNH, Hc,
        (long long)Nc*Sc*Sc, (long long)Sc*Sc, Nc, 1.0f);

    // 4) pos_full = qr . r_head^T per (b,n): [S,H] x [R,H]^T -> [S,R]
    gemm_k<true><<<dim3(Rc/BN, Sc/BM, Bc*Nc), 256>>>(qr, rh, nullptr, pos,
        Sc, Rc, Hc, NHc, NHc, Rc,
        SNH, Hc, 0LL, Hc,
        (long long)Nc*Sc*Rc, (long long)Sc*Rc, Nc, 1.0f);

    // 5) assemble scores (shift + token-type + cls_mask + attention mask)
    combine_k<<<(int)(((long long)Bc*Nc*Sc*Sc)/256), 256>>>(sc, pos, ttd, ttm, clsm, amask);

    // 6) softmax over j (in place)
    softmax_k<<<Bc*Nc*Sc, 256>>>(sc);

    // 7) attn_vec = prob @ v per (b,n): [S,S] x [S,H] -> [S,H] into [B,S,N,H]
    gemm_k<false><<<dim3(Hc/BN, Sc/BM, Bc*Nc), 256>>>(sc, v, nullptr, av,
        Sc, Hc, Sc, Sc, NHc, NHc,
        (long long)Nc*Sc*Sc, (long long)Sc*Sc,
        SNH, Hc, SNH, Hc, Nc, 1.0f);

    // 8) output projection: [2048,1024] @ [1024,1024] + bo
    gemm_k<false><<<dim3(Dc/BN, (Bc*Sc)/BM, 1), 256>>>(av, Wo, bo, ao,
        Bc*Sc, Dc, NHc, NHc, Dc, Dc, 0,0,0,0,0,0, 1, 1.0f);

    // 9) residual + LayerNorm -> d_out
    ln_k<<<Bc*Sc, 256>>>(query, ao, gamma, beta, out);

    (void)in_sizes; (void)n_in; (void)out_size;
}

// round 2
// speedup vs baseline: 1.7512x; 1.7512x over previous
#include <cuda_runtime.h>
#include <cuda_bf16.h>
#include <math.h>
#include <stdint.h>

#define Bc  2
#define Sc  1024
#define Dc  1024
#define Nc  16
#define Hc  64
#define NHc 1024
#define Rc  2048
#define SCALE 0.125f
#define INFV  1000000.0f
#define EPSV  1e-9f
#define SNH ((long long)Sc * NHc)

// ------------------------- scratch -------------------------
__device__ float g_q [Bc*Sc*NHc];               // scaled q projection
__device__ float g_k [Bc*Sc*NHc];
__device__ float g_v [Bc*Sc*NHc];
__device__ float g_rh[Rc*NHc];
__device__ float g_sc[(long long)Bc*Nc*Sc*Sc];  // scores / probs (134MB)
__device__ float g_rwk[Bc*Nc*Sc];               // SCALE*rwb.k  per (b,n,j)
__device__ float g_rrt[Nc*Rc];                  // SCALE*rrb.rh per (n,t)
__device__ float g_ttd[Bc*Sc*Nc*2];             // (diff,same) per (b,i,n)
__device__ float g_av[Bc*Sc*NHc];
__device__ float g_ao[Bc*Sc*Dc];

// ------------------------- mma helpers -------------------------
__device__ __forceinline__ uint32_t cvta_s(const void* p) {
    return (uint32_t)__cvta_generic_to_shared(p);
}
__device__ __forceinline__ void ldm_x4(uint32_t* r, uint32_t a) {
    asm volatile("ldmatrix.sync.aligned.m8n8.x4.shared.b16 {%0,%1,%2,%3}, [%4];"
                 : "=r"(r[0]), "=r"(r[1]), "=r"(r[2]), "=r"(r[3]) : "r"(a));
}
__device__ __forceinline__ void ldm_x2t(uint32_t* r, uint32_t a) {
    asm volatile("ldmatrix.sync.aligned.m8n8.x2.trans.shared.b16 {%0,%1}, [%2];"
                 : "=r"(r[0]), "=r"(r[1]) : "r"(a));
}
__device__ __forceinline__ void mma16816(float* d, const uint32_t* a, const uint32_t* b) {
    asm volatile("mma.sync.aligned.m16n8k16.row.col.f32.bf16.bf16.f32 "
                 "{%0,%1,%2,%3}, {%4,%5,%6,%7}, {%8,%9}, {%0,%1,%2,%3};"
                 : "+f"(d[0]), "+f"(d[1]), "+f"(d[2]), "+f"(d[3])
                 : "r"(a[0]), "r"(a[1]), "r"(a[2]), "r"(a[3]), "r"(b[0]), "r"(b[1]));
}
// split x,y into bf16 hi pair (packed u32) and float residuals
__device__ __forceinline__ void split2(float x, float y, uint32_t& hi, float& lx, float& ly) {
    __nv_bfloat16 hx = __float2bfloat16(x), hy = __float2bfloat16(y);
    __nv_bfloat162 h; h.x = hx; h.y = hy;
    hi = *reinterpret_cast<uint32_t*>(&h);
    lx = x - __bfloat162float(hx);
    ly = y - __bfloat162float(hy);
}
__device__ __forceinline__ uint32_t pack_bf(float x, float y) {
    __nv_bfloat16 hx = __float2bfloat16(x), hy = __float2bfloat16(y);
    __nv_bfloat162 h; h.x = hx; h.y = hy;
    return *reinterpret_cast<uint32_t*>(&h);
}

#define ASTRIDE 40   // bf16 per As row (32 data [hi|lo] + 8 pad)

// ------------------------- tensor GEMM -------------------------
// BM=128, warps 2(m) x 4(n), warp tile 64 x (BN/4). 3x split-bf16 passes.
// EPI 0: C = alpha*acc + bias[j]                 (proj GEMMs, grid.z=1)
// EPI 1: content -> sc: acc + rwk + tt*cls - INF*(1-mask)
// EPI 2: pos band -> sc[i][t+i-1024] += (acc+rrt)*cls
// EPI 3: PV -> av (plain store)
template<int BN, int NT_, bool TRANSB, int EPI>
__global__ __launch_bounds__(256)
void tgemm(const float* __restrict__ A, const float* __restrict__ B,
           const float* __restrict__ bias, float* __restrict__ C,
           int K, int lda, int ldb, int ldc, float alpha,
           const float* __restrict__ aux, const float* __restrict__ ttd,
           const unsigned char* __restrict__ ttm,
           const float* __restrict__ clsm, const int* __restrict__ amask)
{
    constexpr int BSTR = BN + 8;
    const int m0 = blockIdx.y * 128;
    const int n0 = blockIdx.x * BN;
    const int z  = blockIdx.z;
    int bb = 0, nn = 0;
    long long offA = 0, offB = 0, offC = 0;
    if (EPI == 1) { bb = z >> 4; nn = z & 15; offA = (long long)bb*SNH + nn*64; offB = offA; offC = (long long)z*Sc*Sc; }
    if (EPI == 2) { bb = z >> 4; nn = z & 15; offA = (long long)bb*SNH + nn*64; offB = (long long)nn*64; offC = (long long)z*Sc*Sc;
                    // band check: need t+i in [1024, 2047]
                    if (n0 + m0 + 254 < 1024 || n0 + m0 > 2047) return; }
    if (EPI == 3) { bb = z >> 4; nn = z & 15; offA = (long long)z*Sc*Sc; offB = (long long)bb*SNH + nn*64; offC = offB; }
    A += offA; B += offB; C += offC;

    __shared__ __nv_bfloat16 As[128 * ASTRIDE];
    __shared__ __nv_bfloat16 Bs[32 * BSTR];

    const int t    = threadIdx.x;
    const int lane = t & 31;
    const int warp = t >> 5;
    const int wm   = warp >> 2;   // 0..1
    const int wn   = warp & 3;    // 0..3

    float acc[4][NT_][4];
    #pragma unroll
    for (int a = 0; a < 4; ++a)
        #pragma unroll
        for (int b = 0; b < NT_; ++b)
            #pragma unroll
            for (int c = 0; c < 4; ++c) acc[a][b][c] = 0.f;

    // frag base addresses
    const uint32_t aB = cvta_s(As) + (((wm*64 + (lane & 15)) * ASTRIDE + ((lane >> 4) * 8)) << 1);
    const uint32_t bB = cvta_s(Bs) + (((lane & 15) * BSTR + wn * (BN / 4)) << 1);

    for (int k0 = 0; k0 < K; k0 += 16) {
        // ---- stage A: 128 rows x 16 k ----
        {
            int ar = t >> 2, ak = (t & 3) * 4;
            #pragma unroll
            for (int p = 0; p < 128; p += 64) {
                const float4 v = *reinterpret_cast<const float4*>(A + (long long)(m0 + ar + p) * lda + k0 + ak);
                uint32_t h01, h23; float l0, l1, l2, l3;
                split2(v.x, v.y, h01, l0, l1);
                split2(v.z, v.w, h23, l2, l3);
                uint2* dh = reinterpret_cast<uint2*>(&As[(ar + p) * ASTRIDE + ak]);
                *dh = make_uint2(h01, h23);
                uint2* dl = reinterpret_cast<uint2*>(&As[(ar + p) * ASTRIDE + 16 + ak]);
                *dl = make_uint2(pack_bf(l0, l1), pack_bf(l2, l3));
            }
        }
        // ---- stage B ----
        if (TRANSB) { // B[N,K], want Bs[k][n]
            int bn = t >> 2, bkq = (t & 3) * 4;
            #pragma unroll
            for (int p = 0; p < BN; p += 64) {
                const float4 v = *reinterpret_cast<const float4*>(B + (long long)(n0 + bn + p) * ldb + k0 + bkq);
                float xs[4] = {v.x, v.y, v.z, v.w};
                #pragma unroll
                for (int c = 0; c < 4; ++c) {
                    __nv_bfloat16 h = __float2bfloat16(xs[c]);
                    float lo = xs[c] - __bfloat162float(h);
                    Bs[(bkq + c) * BSTR + bn + p] = h;
                    Bs[(16 + bkq + c) * BSTR + bn + p] = __float2bfloat16(lo);
                }
            }
        } else {     // B[K,N], want Bs[k][n]
            int bk = t >> 4, bn = (t & 15) * 4;
            #pragma unroll
            for (int p = 0; p < BN; p += 64) {
                const float4 v = *reinterpret_cast<const float4*>(B + (long long)(k0 + bk) * ldb + n0 + bn + p);
                uint32_t h01, h23; float l0, l1, l2, l3;
                split2(v.x, v.y, h01, l0, l1);
                split2(v.z, v.w, h23, l2, l3);
                *reinterpret_cast<uint2*>(&Bs[bk * BSTR + bn + p]) = make_uint2(h01, h23);
                *reinterpret_cast<uint2*>(&Bs[(16 + bk) * BSTR + bn + p]) =
                    make_uint2(pack_bf(l0, l1), pack_bf(l2, l3));
            }
        }
        __syncthreads();

        // ---- mma: (Ahi,Bhi), (Ahi,Blo), (Alo,Bhi) ----
        uint32_t bh[NT_][2], bl[NT_][2], af[4][4];
        #pragma unroll
        for (int nt = 0; nt < NT_; ++nt) {
            ldm_x2t(bh[nt], bB + nt * 16);
            ldm_x2t(bl[nt], bB + 16 * BSTR * 2 + nt * 16);
        }
        #pragma unroll
        for (int mt = 0; mt < 4; ++mt) ldm_x4(af[mt], aB + mt * (16 * ASTRIDE * 2));
        #pragma unroll
        for (int mt = 0; mt < 4; ++mt)
            #pragma unroll
            for (int nt = 0; nt < NT_; ++nt) mma16816(acc[mt][nt], af[mt], bh[nt]);
        #pragma unroll
        for (int mt = 0; mt < 4; ++mt)
            #pragma unroll
            for (int nt = 0; nt < NT_; ++nt) mma16816(acc[mt][nt], af[mt], bl[nt]);
        #pragma unroll
        for (int mt = 0; mt < 4; ++mt) ldm_x4(af[mt], aB + mt * (16 * ASTRIDE * 2) + 32);
        #pragma unroll
        for (int mt = 0; mt < 4; ++mt)
            #pragma unroll
            for (int nt = 0; nt < NT_; ++nt) mma16816(acc[mt][nt], af[mt], bh[nt]);
        __syncthreads();
    }

    // ---- epilogue ----
    #pragma unroll
    for (int mt = 0; mt < 4; ++mt)
        #pragma unroll
        for (int r2 = 0; r2 < 2; ++r2) {
            const int i = m0 + wm * 64 + mt * 16 + (lane >> 2) + r2 * 8;
            float td0 = 0.f, td1 = 0.f;
            if (EPI == 1) {
                long long tb = (((long long)bb * Sc + i) * Nc + nn) * 2;
                td0 = ttd[tb]; td1 = ttd[tb + 1];
            }
            #pragma unroll
            for (int nt = 0; nt < NT_; ++nt)
                #pragma unroll
                for (int c2 = 0; c2 < 2; ++c2) {
                    const int j = n0 + wn * (BN / 4) + nt * 8 + ((lane & 3) << 1) + c2;
                    float v = acc[mt][nt][r2 * 2 + c2];
                    if (EPI == 0) {
                        v *= alpha;
                        if (bias) v += bias[j];
                        C[(long long)i * ldc + j] = v;
                    } else if (EPI == 1) {
                        v += aux[(long long)z * Sc + j];
                        float tt = ttm[((long long)bb * Sc + i) * Sc + j] ? td1 : td0;
                        v += tt * clsm[(long long)i * Sc + j];
                        v -= INFV * (1.0f - (float)amask[bb * Sc + j]);
                        C[(long long)i * ldc + j] = v;
                    } else if (EPI == 2) {
                        const int jj = j + i - Sc;   // j here is t in [0,R)
                        if (jj >= 0 && jj < Sc) {
                            float pv = (v + aux[nn * Rc + j]) * clsm[(long long)i * Sc + jj];
                            C[(long long)i * ldc + jj] += pv;
                        }
                    } else { // EPI 3
                        C[(long long)i * ldc + j] = v;
                    }
                }
        }
}

// ------------------------- small dot kernels -------------------------
__global__ void rwk_k(const float* __restrict__ k, const float* __restrict__ rwb,
                      float* __restrict__ rwk)
{
    int gw = (blockIdx.x * blockDim.x + threadIdx.x) >> 5;
    int lane = threadIdx.x & 31;
    if (gw >= Bc * Nc * Sc) return;
    int z = gw >> 10, j = gw & (Sc - 1);
    int b = z >> 4, n = z & 15;
    const float* kp = k + (long long)b * SNH + (long long)j * NHc + n * Hc;
    float d = 0.f;
    #pragma unroll
    for (int h = lane; h < Hc; h += 32) d += rwb[n * Hc + h] * kp[h];
    #pragma unroll
    for (int o = 16; o; o >>= 1) d += __shfl_down_sync(0xffffffffu, d, o);
    if (lane == 0) rwk[gw] = d * SCALE;
}

__global__ void rrt_k(const float* __restrict__ rh, const float* __restrict__ rrb,
                      float* __restrict__ rrt)
{
    int gw = (blockIdx.x * blockDim.x + threadIdx.x) >> 5;
    int lane = threadIdx.x & 31;
    if (gw >= Nc * Rc) return;
    int n = gw >> 11, tt = gw & (Rc - 1);
    const float* rp = rh + (long long)tt * NHc + n * Hc;
    float d = 0.f;
    #pragma unroll
    for (int h = lane; h < Hc; h += 32) d += rrb[n * Hc + h] * rp[h];
    #pragma unroll
    for (int o = 16; o; o >>= 1) d += __shfl_down_sync(0xffffffffu, d, o);
    if (lane == 0) rrt[gw] = d * SCALE;
}

__global__ void ttd_k(const float* __restrict__ q, const float* __restrict__ seg,
                      const float* __restrict__ rsb, float* __restrict__ ttd)
{
    int gw = (blockIdx.x * blockDim.x + threadIdx.x) >> 5;
    int lane = threadIdx.x & 31;
    if (gw >= Bc * Sc * Nc) return;
    int n = gw & 15;
    long long bi = gw >> 4;
    const float* qp = q + bi * NHc + n * Hc;
    float d0 = 0.f, d1 = 0.f, s0 = 0.f, s1 = 0.f;
    #pragma unroll
    for (int h = lane; h < Hc; h += 32) {
        float e0 = seg[n * Hc + h], e1 = seg[Nc * Hc + n * Hc + h];
        float qv = qp[h], rv = rsb[n * Hc + h];
        d0 += qv * e0; d1 += qv * e1;
        s0 += rv * e0; s1 += rv * e1;
    }
    #pragma unroll
    for (int o = 16; o; o >>= 1) {
        d0 += __shfl_down_sync(0xffffffffu, d0, o);
        d1 += __shfl_down_sync(0xffffffffu, d1, o);
        s0 += __shfl_down_sync(0xffffffffu, s0, o);
        s1 += __shfl_down_sync(0xffffffffu, s1, o);
    }
    if (lane == 0) {
        ttd[2 * gw]     = d0 + SCALE * s0;   // diff (seg 0)
        ttd[2 * gw + 1] = d1 + SCALE * s1;   // same (seg 1)
    }
}

// ------------------------- softmax / layernorm -------------------------
__global__ void softmax_k(float* __restrict__ sc)
{
    __shared__ float red[256];
    float* p = sc + (long long)blockIdx.x * Sc;
    int t = threadIdx.x;
    float v[4]; float m = -3.4e38f;
    #pragma unroll
    for (int u = 0; u < 4; ++u) { v[u] = p[t + u * 256]; m = fmaxf(m, v[u]); }
    red[t] = m; __syncthreads();
    #pragma unroll
    for (int s = 128; s; s >>= 1) { if (t < s) red[t] = fmaxf(red[t], red[t + s]); __syncthreads(); }
    m = red[0]; __syncthreads();
    float sum = 0.f;
    #pragma unroll
    for (int u = 0; u < 4; ++u) { v[u] = expf(v[u] - m); sum += v[u]; }
    red[t] = sum; __syncthreads();
    #pragma unroll
    for (int s = 128; s; s >>= 1) { if (t < s) red[t] += red[t + s]; __syncthreads(); }
    float inv = 1.0f / red[0];
    #pragma unroll
    for (int u = 0; u < 4; ++u) p[t + u * 256] = v[u] * inv;
}

__global__ void ln_k(const float* __restrict__ query, const float* __restrict__ ao,
                     const float* __restrict__ gamma, const float* __restrict__ beta,
                     float* __restrict__ out)
{
    __shared__ float red[256];
    long long base = (long long)blockIdx.x * Dc;
    int t = threadIdx.x;
    float x[4]; float s = 0.f;
    #pragma unroll
    for (int u = 0; u < 4; ++u) { x[u] = query[base + t + u * 256] + ao[base + t + u * 256]; s += x[u]; }
    red[t] = s; __syncthreads();
    #pragma unroll
    for (int o = 128; o; o >>= 1) { if (t < o) red[t] += red[t + o]; __syncthreads(); }
    float mu = red[0] * (1.0f / Dc); __syncthreads();
    float s2 = 0.f;
    #pragma unroll
    for (int u = 0; u < 4; ++u) { float d = x[u] - mu; s2 += d * d; }
    red[t] = s2; __syncthreads();
    #pragma unroll
    for (int o = 128; o; o >>= 1) { if (t < o) red[t] += red[t + o]; __syncthreads(); }
    float inv = rsqrtf(red[0] * (1.0f / Dc) + EPSV);
    #pragma unroll
    for (int u = 0; u < 4; ++u) {
        int c = t + u * 256;
        out[base + c] = (x[u] - mu) * inv * gamma[c] + beta[c];
    }
}

// ------------------------- driver -------------------------
extern "C" void kernel_launch(void* const* d_in, const int* in_sizes, int n_in,
                              void* d_out, int out_size)
{
    const float* query = (const float*)d_in[0];
    const float* key   = (const float*)d_in[1];
    const float* value = (const float*)d_in[2];
    const float* r     = (const float*)d_in[3];
    const float* clsm  = (const float*)d_in[4];
    const float* Wq    = (const float*)d_in[5];
    const float* Wk    = (const float*)d_in[6];
    const float* bk    = (const float*)d_in[7];
    const float* Wv    = (const float*)d_in[8];
    const float* bv    = (const float*)d_in[9];
    const float* Wo    = (const float*)d_in[10];
    const float* bo    = (const float*)d_in[11];
    const float* rwb   = (const float*)d_in[12];
    const float* rrb   = (const float*)d_in[13];
    const float* rkern = (const float*)d_in[14];
    const float* rsb   = (const float*)d_in[15];
    const float* seg   = (const float*)d_in[16];
    const float* gamma = (const float*)d_in[17];
    const float* beta  = (const float*)d_in[18];
    const unsigned char* ttm = (const unsigned char*)d_in[19];
    const int*   amask = (const int*)d_in[20];
    float* out = (float*)d_out;

    float *q, *k, *v, *rh, *sc, *rwk, *rrt, *ttd, *av, *ao;
    cudaGetSymbolAddress((void**)&q,   g_q);
    cudaGetSymbolAddress((void**)&k,   g_k);
    cudaGetSymbolAddress((void**)&v,   g_v);
    cudaGetSymbolAddress((void**)&rh,  g_rh);
    cudaGetSymbolAddress((void**)&sc,  g_sc);
    cudaGetSymbolAddress((void**)&rwk, g_rwk);
    cudaGetSymbolAddress((void**)&rrt, g_rrt);
    cudaGetSymbolAddress((void**)&ttd, g_ttd);
    cudaGetSymbolAddress((void**)&av,  g_av);
    cudaGetSymbolAddress((void**)&ao,  g_ao);

    // 1) projections  (M=2048 x N=1024 x K=1024)
    tgemm<128,4,false,0><<<dim3(8,16,1), 256>>>(query, Wq, nullptr, q, Dc, Dc, NHc, NHc, SCALE,
                                                nullptr, nullptr, nullptr, nullptr, nullptr);
    tgemm<128,4,false,0><<<dim3(8,16,1), 256>>>(key,   Wk, bk,     k, Dc, Dc, NHc, NHc, 1.0f,
                                                nullptr, nullptr, nullptr, nullptr, nullptr);
    tgemm<128,4,false,0><<<dim3(8,16,1), 256>>>(value, Wv, bv,     v, Dc, Dc, NHc, NHc, 1.0f,
                                                nullptr, nullptr, nullptr, nullptr, nullptr);
    tgemm<128,4,false,0><<<dim3(8,16,1), 256>>>(r, rkern, nullptr, rh, Dc, Dc, NHc, NHc, 1.0f,
                                                nullptr, nullptr, nullptr, nullptr, nullptr);

    // 2) tiny bias-dot tables
    rwk_k<<<4096, 256>>>(k, rwb, rwk);
    rrt_k<<<4096, 256>>>(rh, rrb, rrt);
    ttd_k<<<4096, 256>>>(q, seg, rsb, ttd);

    // 3) content scores + tt + mask  (per bn: 1024x1024x64, NT)
    tgemm<128,4,true,1><<<dim3(8,8,Bc*Nc), 256>>>(q, k, nullptr, sc, Hc, NHc, NHc, Sc, 1.0f,
                                                  rwk, ttd, ttm, clsm, amask);

    // 4) pos band: sc += shifted(q . rh^T)  (per bn: 1024x2048x64, NT, band-skipped)
    tgemm<128,4,true,2><<<dim3(16,8,Bc*Nc), 256>>>(q, rh, nullptr, sc, Hc, NHc, NHc, Sc, 1.0f,
                                                   rrt, nullptr, nullptr, clsm, nullptr);

    // 5) softmax
    softmax_k<<<Bc*Nc*Sc, 256>>>(sc);

    // 6) PV  (per bn: 1024x64x1024, NN)
    tgemm<64,2,false,3><<<dim3(1,8,Bc*Nc), 256>>>(sc, v, nullptr, av, Sc, Sc, NHc, NHc, 1.0f,
                                                  nullptr, nullptr, nullptr, nullptr, nullptr);

    // 7) output projection (2048x1024x1024) + bias
    tgemm<128,4,false,0><<<dim3(8,16,1), 256>>>(av, Wo, bo, ao, NHc, NHc, Dc, Dc, 1.0f,
                                                nullptr, nullptr, nullptr, nullptr, nullptr);

    // 8) residual + LayerNorm
    ln_k<<<Bc*Sc, 256>>>(query, ao, gamma, beta, out);

    (void)in_sizes; (void)n_in; (void)out_size;
}

// round 3
// speedup vs baseline: 1.9491x; 1.1130x over previous
#include <cuda_runtime.h>
#include <cuda_bf16.h>
#include <math.h>
#include <stdint.h>

#define Bc 2
#define Sc 1024
#define Dc 1024
#define Nc 16
#define Hc 64
#define NHc 1024
#define Rc 2048
#define SCALE 0.125f
#define INFV 1000000.0f
#define EPSV 1e-9f

typedef __nv_bfloat16 bf;

// ------------------------- scratch -------------------------
__device__ bf g_qy2[2048*2048];   // query split [M,2K]
__device__ bf g_ky2[2048*2048];
__device__ bf g_vy2[2048*2048];
__device__ bf g_r2 [2048*2048];
__device__ bf g_Wq2[2048*1024];   // weights split [2K,N]
__device__ bf g_Wk2[2048*1024];
__device__ bf g_Wv2[2048*1024];
__device__ bf g_rk2[2048*1024];
__device__ bf g_Wo2[2048*1024];
__device__ bf g_q2 [2048*2048];   // [B*S, N*128] per-head hi|lo
__device__ bf g_k2 [2048*2048];
__device__ bf g_rh2[2048*2048];   // [R, N*128]
__device__ bf g_v2 [2*2048*1024]; // [B, 2S, NH] hi rows | lo rows
__device__ float g_sc[(long long)32*1024*1024];   // 134MB scores
__device__ bf g_p2[(long long)32*1024*2048];      // 134MB probs split [bnS, 2S]
__device__ bf g_av2[2048*2048];   // attn_vec split [M, 2K]
__device__ float g_ao[2048*1024];
__device__ float g_rwk[32*1024];
__device__ float g_rrt[16*2048];
__device__ float g_ttd[2048*16*2];

// ------------------------- helpers -------------------------
__device__ __forceinline__ uint32_t cvta_s(const void* p){ return (uint32_t)__cvta_generic_to_shared(p); }
__device__ __forceinline__ void cp16(uint32_t d, const void* s){
    asm volatile("cp.async.cg.shared.global [%0], [%1], 16;" :: "r"(d), "l"(s));
}
__device__ __forceinline__ void ldm_x4(uint32_t* r, uint32_t a){
    asm volatile("ldmatrix.sync.aligned.m8n8.x4.shared.b16 {%0,%1,%2,%3}, [%4];"
                 : "=r"(r[0]), "=r"(r[1]), "=r"(r[2]), "=r"(r[3]) : "r"(a));
}
__device__ __forceinline__ void ldm_x2t(uint32_t* r, uint32_t a){
    asm volatile("ldmatrix.sync.aligned.m8n8.x2.trans.shared.b16 {%0,%1}, [%2];"
                 : "=r"(r[0]), "=r"(r[1]) : "r"(a));
}
__device__ __forceinline__ void ldm_x2(uint32_t* r, uint32_t a){
    asm volatile("ldmatrix.sync.aligned.m8n8.x2.shared.b16 {%0,%1}, [%2];"
                 : "=r"(r[0]), "=r"(r[1]) : "r"(a));
}
__device__ __forceinline__ void mma16816(float* d, const uint32_t* a, const uint32_t* b){
    asm volatile("mma.sync.aligned.m16n8k16.row.col.f32.bf16.bf16.f32 "
                 "{%0,%1,%2,%3}, {%4,%5,%6,%7}, {%8,%9}, {%0,%1,%2,%3};"
                 : "+f"(d[0]), "+f"(d[1]), "+f"(d[2]), "+f"(d[3])
                 : "r"(a[0]), "r"(a[1]), "r"(a[2]), "r"(a[3]), "r"(b[0]), "r"(b[1]));
}
__device__ __forceinline__ void bsplit(float x, bf& h, bf& l){
    h = __float2bfloat16(x); l = __float2bfloat16(x - __bfloat162float(h));
}

// ------------------------- pre-split conversions -------------------------
// A layout: [M,K] fp32 -> [M,2K] bf16 (hi cols 0..K-1, lo cols K..2K-1). K=1024.
__global__ void splitA_k(const float* __restrict__ in, bf* __restrict__ out){
    int i4 = (blockIdx.x*256 + threadIdx.x)*4;
    float4 v = *(const float4*)(in + i4);
    int row = i4 >> 10, col = i4 & 1023;
    bf* o = out + (long long)row*2048 + col;
    bf h,l;
    bsplit(v.x,h,l); o[0]=h; o[1024+0]=l;
    bsplit(v.y,h,l); o[1]=h; o[1024+1]=l;
    bsplit(v.z,h,l); o[2]=h; o[1024+2]=l;
    bsplit(v.w,h,l); o[3]=h; o[1024+3]=l;
}
// B layout: [K,N] fp32 -> [2K,N] bf16 (hi rows 0..K-1, lo rows K..). K=N=1024.
__global__ void splitB_k(const float* __restrict__ in, bf* __restrict__ out){
    int i4 = (blockIdx.x*256 + threadIdx.x)*4;
    float4 v = *(const float4*)(in + i4);
    bf h,l;
    const long long LO = 1024LL*1024LL;
    bsplit(v.x,h,l); out[i4+0]=h; out[LO+i4+0]=l;
    bsplit(v.y,h,l); out[i4+1]=h; out[LO+i4+1]=l;
    bsplit(v.z,h,l); out[i4+2]=h; out[LO+i4+2]=l;
    bsplit(v.w,h,l); out[i4+3]=h; out[LO+i4+3]=l;
}

// ------------------------- pipelined bf16 tensor GEMM -------------------------
// BM=128, BK=32, 8 warps (2m x 4n). EPI:
//  0: proj -> Cb in [rows, N*128] hi|lo per head (alpha, +bias)
//  5: proj -> v2 [B,2S,NH] row-split (+bias)
//  1: content -> sc fp32 fused (+rwk + tt*cls - INF*(1-mask))
//  2: pos band -> sc RMW shifted
//  3: PV -> av2 split [M,2048]
//  4: outproj -> ao fp32 (+bias)
template<int BN, int NT_, bool TRANSB, int EPI>
__global__ __launch_bounds__(256, 2)
void tgemm2(const bf* __restrict__ A, const bf* __restrict__ B,
            const float* __restrict__ bias, float* __restrict__ Cf, bf* __restrict__ Cb,
            int K, int lda, int ldb, int ldc, float alpha,
            const float* __restrict__ aux, const float* __restrict__ ttd,
            const unsigned char* __restrict__ ttm, const float* __restrict__ clsm,
            const int* __restrict__ amask)
{
    constexpr int BSTR  = TRANSB ? 40 : (BN + 8);
    constexpr int BROWS = TRANSB ? BN : 32;
    const int m0 = blockIdx.y*128, n0 = blockIdx.x*BN, z = blockIdx.z;
    const int bb = z >> 4, nn = z & 15;
    if (EPI == 1){ A += ((long long)bb*Sc)*2048 + nn*128; B += ((long long)bb*Sc)*2048 + nn*128; Cf += (long long)z*Sc*Sc; }
    if (EPI == 2){ if (m0 + n0 + 254 < Sc || m0 + n0 > 2*Sc - 1) return;
                   A += ((long long)bb*Sc)*2048 + nn*128; B += (long long)nn*128; Cf += (long long)z*Sc*Sc; }
    if (EPI == 3){ A += (long long)z*Sc*2048; B += (long long)bb*2048*1024 + nn*64; }

    __shared__ bf As[2][128*40];
    __shared__ bf Bs[2][BROWS*BSTR];

    const int t = threadIdx.x, lane = t & 31, warp = t >> 5, wm = warp >> 2, wn = warp & 3;

    float acc[4][NT_][4];
    #pragma unroll
    for (int a=0;a<4;++a)
        #pragma unroll
        for (int b=0;b<NT_;++b)
            #pragma unroll
            for (int c=0;c<4;++c) acc[a][b][c] = 0.f;

    auto loadA = [&](int s, int k0){
        #pragma unroll
        for (int q=0;q<2;++q){
            int c = t*2+q, row = c>>2, seg = c&3;
            cp16(cvta_s(&As[s][row*40 + seg*8]), A + (long long)(m0+row)*lda + k0 + seg*8);
        }
    };
    auto loadB = [&](int s, int k0){
        if (TRANSB){
            #pragma unroll
            for (int q=0;q<(BN*4)/256;++q){
                int c = t*((BN*4)/256)+q, row = c>>2, seg = c&3;
                cp16(cvta_s(&Bs[s][row*BSTR + seg*8]), B + (long long)(n0+row)*ldb + k0 + seg*8);
            }
        } else {
            constexpr int CPR = BN/8;
            #pragma unroll
            for (int q=0;q<(32*CPR)/256;++q){
                int c = t*((32*CPR)/256)+q, row = c/CPR, seg = c%CPR;
                cp16(cvta_s(&Bs[s][row*BSTR + seg*8]), B + (long long)(k0+row)*ldb + n0 + seg*8);
            }
        }
    };

    const int KT = K/32;
    loadA(0,0); loadB(0,0);
    asm volatile("cp.async.commit_group;");
    for (int kt = 0; kt < KT; ++kt){
        asm volatile("cp.async.wait_group 0;");
        __syncthreads();
        if (kt+1 < KT){ loadA((kt+1)&1, (kt+1)*32); loadB((kt+1)&1, (kt+1)*32);
                        asm volatile("cp.async.commit_group;"); }
        const int s = kt & 1;
        const uint32_t aBase = cvta_s(&As[s][0]) + ((wm*64 + (lane&15))*40)*2;
        const uint32_t bBase = cvta_s(&Bs[s][0]);
        #pragma unroll
        for (int ks = 0; ks < 32; ks += 16){
            uint32_t af[4][4], bfrg[NT_][2];
            #pragma unroll
            for (int mt=0; mt<4; ++mt)
                ldm_x4(af[mt], aBase + (mt*16*40 + ks + (lane>>4)*8)*2);
            #pragma unroll
            for (int nt=0; nt<NT_; ++nt){
                if (TRANSB){
                    int l = lane & 15;
                    ldm_x2(bfrg[nt], bBase + (((wn*(BN/4) + nt*8 + (l&7))*BSTR + ks + (l>>3)*8))*2);
                } else {
                    ldm_x2t(bfrg[nt], bBase + (((ks + (lane&15))*BSTR + wn*(BN/4) + nt*8))*2);
                }
            }
            #pragma unroll
            for (int mt=0; mt<4; ++mt)
                #pragma unroll
                for (int nt=0; nt<NT_; ++nt) mma16816(acc[mt][nt], af[mt], bfrg[nt]);
        }
    }

    // epilogue
    #pragma unroll
    for (int mt=0; mt<4; ++mt)
      #pragma unroll
      for (int r2=0; r2<2; ++r2){
        const int i = m0 + wm*64 + mt*16 + (lane>>2) + r2*8;
        float td0 = 0.f, td1 = 0.f;
        if (EPI == 1){ long long tb = (((long long)bb*Sc + i)*Nc + nn)*2; td0 = ttd[tb]; td1 = ttd[tb+1]; }
        #pragma unroll
        for (int nt=0; nt<NT_; ++nt)
          #pragma unroll
          for (int c2=0; c2<2; ++c2){
            const int j = n0 + wn*(BN/4) + nt*8 + ((lane&3)<<1) + c2;
            float v = acc[mt][nt][r2*2 + c2];
            if (EPI == 0){
                v = v*alpha + (bias ? bias[j] : 0.f);
                bf h,l; bsplit(v,h,l);
                long long base = (long long)i*2048 + (j>>6)*128 + (j&63);
                Cb[base] = h; Cb[base + 64] = l;
            } else if (EPI == 5){
                v += (bias ? bias[j] : 0.f);
                bf h,l; bsplit(v,h,l);
                int b_ = i >> 10, il = i & 1023;
                long long hi = ((long long)(b_*2048 + il))*1024 + j;
                Cb[hi] = h; Cb[hi + 1024LL*1024LL] = l;
            } else if (EPI == 1){
                v += aux[(long long)z*Sc + j];
                float tt = ttm[((long long)bb*Sc + i)*Sc + j] ? td1 : td0;
                v += tt * clsm[(long long)i*Sc + j];
                v -= INFV * (1.0f - (float)amask[bb*Sc + j]);
                Cf[(long long)i*ldc + j] = v;
            } else if (EPI == 2){
                const int jj = j + i - Sc;
                if (jj >= 0 && jj < Sc){
                    float pv = (v + aux[nn*Rc + j]) * clsm[(long long)i*Sc + jj];
                    Cf[(long long)i*ldc + jj] += pv;
                }
            } else if (EPI == 3){
                bf h,l; bsplit(v,h,l);
                long long rb = (long long)(bb*1024 + i);
                int col = nn*64 + j;
                Cb[rb*2048 + col] = h; Cb[rb*2048 + 1024 + col] = l;
            } else { // EPI 4
                Cf[(long long)i*ldc + j] = v + (bias ? bias[j] : 0.f);
            }
          }
      }
}

// ------------------------- small dot kernels (read split bf16) ----------------
__device__ __forceinline__ float rejoin(const bf* p, int h){
    return __bfloat162float(p[h]) + __bfloat162float(p[64 + h]);
}
__global__ void rwk_k(const bf* __restrict__ k2, const float* __restrict__ rwb, float* __restrict__ rwk){
    int gw = (blockIdx.x*blockDim.x + threadIdx.x) >> 5;
    int lane = threadIdx.x & 31;
    if (gw >= Bc*Nc*Sc) return;
    int z = gw >> 10, j = gw & (Sc-1);
    int b = z >> 4, n = z & 15;
    const bf* kp = k2 + ((long long)(b*1024 + j))*2048 + n*128;
    float d = 0.f;
    #pragma unroll
    for (int h = lane; h < Hc; h += 32) d += rwb[n*Hc + h] * rejoin(kp, h);
    #pragma unroll
    for (int o = 16; o; o >>= 1) d += __shfl_down_sync(0xffffffffu, d, o);
    if (lane == 0) rwk[gw] = d * SCALE;
}
__global__ void rrt_k(const bf* __restrict__ rh2, const float* __restrict__ rrb, float* __restrict__ rrt){
    int gw = (blockIdx.x*blockDim.x + threadIdx.x) >> 5;
    int lane = threadIdx.x & 31;
    if (gw >= Nc*Rc) return;
    int n = gw >> 11, tt = gw & (Rc-1);
    const bf* rp = rh2 + (long long)tt*2048 + n*128;
    float d = 0.f;
    #pragma unroll
    for (int h = lane; h < Hc; h += 32) d += rrb[n*Hc + h] * rejoin(rp, h);
    #pragma unroll
    for (int o = 16; o; o >>= 1) d += __shfl_down_sync(0xffffffffu, d, o);
    if (lane == 0) rrt[gw] = d * SCALE;
}
__global__ void ttd_k(const bf* __restrict__ q2, const float* __restrict__ seg,
                      const float* __restrict__ rsb, float* __restrict__ ttd){
    int gw = (blockIdx.x*blockDim.x + threadIdx.x) >> 5;
    int lane = threadIdx.x & 31;
    if (gw >= Bc*Sc*Nc) return;
    int n = gw & 15;
    long long bi = gw >> 4;
    const bf* qp = q2 + bi*2048 + n*128;
    float d0=0.f, d1=0.f, s0=0.f, s1=0.f;
    #pragma unroll
    for (int h = lane; h < Hc; h += 32){
        float e0 = seg[n*Hc + h], e1 = seg[Nc*Hc + n*Hc + h];
        float qv = rejoin(qp, h), rv = rsb[n*Hc + h];
        d0 += qv*e0; d1 += qv*e1; s0 += rv*e0; s1 += rv*e1;
    }
    #pragma unroll
    for (int o = 16; o; o >>= 1){
        d0 += __shfl_down_sync(0xffffffffu, d0, o);
        d1 += __shfl_down_sync(0xffffffffu, d1, o);
        s0 += __shfl_down_sync(0xffffffffu, s0, o);
        s1 += __shfl_down_sync(0xffffffffu, s1, o);
    }
    if (lane == 0){ ttd[2*gw] = d0 + SCALE*s0; ttd[2*gw+1] = d1 + SCALE*s1; }
}

// ------------------------- softmax -> split bf16 probs -------------------------
__global__ void softmax_k(const float* __restrict__ sc, bf* __restrict__ p2){
    __shared__ float red[256];
    long long row = blockIdx.x;
    const float* p = sc + row*Sc;
    bf* o = p2 + row*2048;
    int t = threadIdx.x;
    float v[4]; float m = -3.4e38f;
    #pragma unroll
    for (int u=0;u<4;++u){ v[u] = p[t + u*256]; m = fmaxf(m, v[u]); }
    red[t] = m; __syncthreads();
    #pragma unroll
    for (int s=128; s; s>>=1){ if (t < s) red[t] = fmaxf(red[t], red[t+s]); __syncthreads(); }
    m = red[0]; __syncthreads();
    float sum = 0.f;
    #pragma unroll
    for (int u=0;u<4;++u){ v[u] = expf(v[u] - m); sum += v[u]; }
    red[t] = sum; __syncthreads();
    #pragma unroll
    for (int s=128; s; s>>=1){ if (t < s) red[t] += red[t+s]; __syncthreads(); }
    float inv = 1.0f / red[0];
    #pragma unroll
    for (int u=0;u<4;++u){
        float x = v[u]*inv;
        bf h,l; bsplit(x,h,l);
        o[t + u*256] = h; o[1024 + t + u*256] = l;
    }
}

// ------------------------- residual + LayerNorm -------------------------
__global__ void ln_k(const float* __restrict__ query, const float* __restrict__ ao,
                     const float* __restrict__ gamma, const float* __restrict__ beta,
                     float* __restrict__ out){
    __shared__ float red[256];
    long long base = (long long)blockIdx.x * Dc;
    int t = threadIdx.x;
    float x[4]; float s = 0.f;
    #pragma unroll
    for (int u=0;u<4;++u){ x[u] = query[base + t + u*256] + ao[base + t + u*256]; s += x[u]; }
    red[t] = s; __syncthreads();
    #pragma unroll
    for (int o=128; o; o>>=1){ if (t < o) red[t] += red[t+o]; __syncthreads(); }
    float mu = red[0] * (1.0f/Dc); __syncthreads();
    float s2 = 0.f;
    #pragma unroll
    for (int u=0;u<4;++u){ float d = x[u]-mu; s2 += d*d; }
    red[t] = s2; __syncthreads();
    #pragma unroll
    for (int o=128; o; o>>=1){ if (t < o) red[t] += red[t+o]; __syncthreads(); }
    float inv = rsqrtf(red[0]*(1.0f/Dc) + EPSV);
    #pragma unroll
    for (int u=0;u<4;++u){
        int c = t + u*256;
        out[base + c] = (x[u]-mu)*inv*gamma[c] + beta[c];
    }
}

// ------------------------- driver -------------------------
extern "C" void kernel_launch(void* const* d_in, const int* in_sizes, int n_in,
                              void* d_out, int out_size)
{
    const float* query = (const float*)d_in[0];
    const float* key   = (const float*)d_in[1];
    const float* value = (const float*)d_in[2];
    const float* r     = (const float*)d_in[3];
    const float* clsm  = (const float*)d_in[4];
    const float* Wq    = (const float*)d_in[5];
    const float* Wk    = (const float*)d_in[6];
    const float* bk    = (const float*)d_in[7];
    const float* Wv    = (const float*)d_in[8];
    const float* bv    = (const float*)d_in[9];
    const float* Wo    = (const float*)d_in[10];
    const float* bo    = (const float*)d_in[11];
    const float* rwb   = (const float*)d_in[12];
    const float* rrb   = (const float*)d_in[13];
    const float* rkern = (const float*)d_in[14];
    const float* rsb   = (const float*)d_in[15];
    const float* seg   = (const float*)d_in[16];
    const float* gamma = (const float*)d_in[17];
    const float* beta  = (const float*)d_in[18];
    const unsigned char* ttm = (const unsigned char*)d_in[19];
    const int*   amask = (const int*)d_in[20];
    float* out = (float*)d_out;

    bf *qy2,*ky2,*vy2,*r2,*Wq2,*Wk2,*Wv2,*rk2,*Wo2,*q2,*k2,*rh2,*v2,*p2,*av2;
    float *sc,*ao,*rwk,*rrt,*ttd;
    cudaGetSymbolAddress((void**)&qy2, g_qy2);
    cudaGetSymbolAddress((void**)&ky2, g_ky2);
    cudaGetSymbolAddress((void**)&vy2, g_vy2);
    cudaGetSymbolAddress((void**)&r2,  g_r2);
    cudaGetSymbolAddress((void**)&Wq2, g_Wq2);
    cudaGetSymbolAddress((void**)&Wk2, g_Wk2);
    cudaGetSymbolAddress((void**)&Wv2, g_Wv2);
    cudaGetSymbolAddress((void**)&rk2, g_rk2);
    cudaGetSymbolAddress((void**)&Wo2, g_Wo2);
    cudaGetSymbolAddress((void**)&q2,  g_q2);
    cudaGetSymbolAddress((void**)&k2,  g_k2);
    cudaGetSymbolAddress((void**)&rh2, g_rh2);
    cudaGetSymbolAddress((void**)&v2,  g_v2);
    cudaGetSymbolAddress((void**)&p2,  g_p2);
    cudaGetSymbolAddress((void**)&av2, g_av2);
    cudaGetSymbolAddress((void**)&sc,  g_sc);
    cudaGetSymbolAddress((void**)&ao,  g_ao);
    cudaGetSymbolAddress((void**)&rwk, g_rwk);
    cudaGetSymbolAddress((void**)&rrt, g_rrt);
    cudaGetSymbolAddress((void**)&ttd, g_ttd);

    // 0) pre-split inputs/weights
    splitA_k<<<2048, 256>>>(query, qy2);
    splitA_k<<<2048, 256>>>(key,   ky2);
    splitA_k<<<2048, 256>>>(value, vy2);
    splitA_k<<<2048, 256>>>(r,     r2);
    splitB_k<<<1024, 256>>>(Wq, Wq2);
    splitB_k<<<1024, 256>>>(Wk, Wk2);
    splitB_k<<<1024, 256>>>(Wv, Wv2);
    splitB_k<<<1024, 256>>>(rkern, rk2);
    splitB_k<<<1024, 256>>>(Wo, Wo2);

    // 1) projections (M=2048, N=1024, K'=2048) -> split outputs
    tgemm2<128,4,false,0><<<dim3(8,16,1), 256>>>(qy2, Wq2, nullptr, nullptr, q2,
        2048, 2048, 1024, 0, SCALE, nullptr,nullptr,nullptr,nullptr,nullptr);
    tgemm2<128,4,false,0><<<dim3(8,16,1), 256>>>(ky2, Wk2, bk, nullptr, k2,
        2048, 2048, 1024, 0, 1.0f, nullptr,nullptr,nullptr,nullptr,nullptr);
    tgemm2<128,4,false,5><<<dim3(8,16,1), 256>>>(vy2, Wv2, bv, nullptr, v2,
        2048, 2048, 1024, 0, 1.0f, nullptr,nullptr,nullptr,nullptr,nullptr);
    tgemm2<128,4,false,0><<<dim3(8,16,1), 256>>>(r2, rk2, nullptr, nullptr, rh2,
        2048, 2048, 1024, 0, 1.0f, nullptr,nullptr,nullptr,nullptr,nullptr);

    // 2) tiny bias-dot tables
    rwk_k<<<4096, 256>>>(k2, rwb, rwk);
    rrt_k<<<4096, 256>>>(rh2, rrb, rrt);
    ttd_k<<<4096, 256>>>(q2, seg, rsb, ttd);

    // 3) content scores fused (per bn: 1024x1024, K'=128, NT)
    tgemm2<128,4,true,1><<<dim3(8,8,Bc*Nc), 256>>>(q2, k2, nullptr, sc, nullptr,
        128, 2048, 2048, 1024, 1.0f, rwk, ttd, ttm, clsm, amask);

    // 4) pos band RMW (per bn: 1024x2048, K'=128, NT, band skip)
    tgemm2<128,4,true,2><<<dim3(16,8,Bc*Nc), 256>>>(q2, rh2, nullptr, sc, nullptr,
        128, 2048, 2048, 1024, 1.0f, rrt, nullptr, nullptr, clsm, nullptr);

    // 5) softmax -> split bf16 probs
    softmax_k<<<Bc*Nc*Sc, 256>>>(sc, p2);

    // 6) PV (per bn: 1024x64, K'=2048, NN) -> av2 split
    tgemm2<64,2,false,3><<<dim3(1,8,Bc*Nc), 256>>>(p2, v2, nullptr, nullptr, av2,
        2048, 2048, 1024, 0, 1.0f, nullptr,nullptr,nullptr,nullptr,nullptr);

    // 7) output projection (2048x1024, K'=2048) + bias -> ao fp32
    tgemm2<128,4,false,4><<<dim3(8,16,1), 256>>>(av2, Wo2, bo, ao, nullptr,
        2048, 2048, 1024, 1024, 1.0f, nullptr,nullptr,nullptr,nullptr,nullptr);

    // 8) residual + LayerNorm
    ln_k<<<Bc*Sc, 256>>>(query, ao, gamma, beta, out);

    (void)in_sizes; (void)n_in; (void)out_size;
}

// round 4
// speedup vs baseline: 2.5905x; 1.3291x over previous
#include <cuda_runtime.h>
#include <cuda_bf16.h>
#include <math.h>
#include <stdint.h>

#define Bc 2
#define Sc 1024
#define Dc 1024
#define Nc 16
#define Hc 64
#define NHc 1024
#define Rc 2048
#define SCALE 0.125f
#define INFV 1000000.0f
#define EPSV 1e-9f

typedef __nv_bfloat16 bf;

// ------------------------- scratch -------------------------
__device__ bf g_in16[4 * 2048 * 1024];   // query,key,value,r as bf16 [2048,1024]
__device__ bf g_w16 [5 * 1024 * 1024];   // Wq,Wk,Wv,rkern,Wo as bf16 [1024,1024]
__device__ bf g_proj[4 * 2048 * 1024];   // q16,k16,v16,rh16 [2048,1024]
__device__ float g_sc[(long long)32 * 1024 * 1024];  // scores fp32
__device__ bf g_p16[(long long)32 * 1024 * 1024];    // probs bf16
__device__ bf g_av16[2048 * 1024];       // attn_vec bf16 [B*S, NH]
__device__ float g_ao[2048 * 1024];
__device__ float g_rwk[32 * 1024];
__device__ float g_rrt[16 * 2048];
__device__ float g_ttd[2048 * 16 * 2];

// ------------------------- helpers -------------------------
__device__ __forceinline__ uint32_t cvta_s(const void* p){ return (uint32_t)__cvta_generic_to_shared(p); }
__device__ __forceinline__ void cp16(uint32_t d, const void* s){
    asm volatile("cp.async.cg.shared.global [%0], [%1], 16;" :: "r"(d), "l"(s));
}
__device__ __forceinline__ void ldm_x4(uint32_t* r, uint32_t a){
    asm volatile("ldmatrix.sync.aligned.m8n8.x4.shared.b16 {%0,%1,%2,%3}, [%4];"
                 : "=r"(r[0]), "=r"(r[1]), "=r"(r[2]), "=r"(r[3]) : "r"(a));
}
__device__ __forceinline__ void ldm_x2t(uint32_t* r, uint32_t a){
    asm volatile("ldmatrix.sync.aligned.m8n8.x2.trans.shared.b16 {%0,%1}, [%2];"
                 : "=r"(r[0]), "=r"(r[1]) : "r"(a));
}
__device__ __forceinline__ void ldm_x2(uint32_t* r, uint32_t a){
    asm volatile("ldmatrix.sync.aligned.m8n8.x2.shared.b16 {%0,%1}, [%2];"
                 : "=r"(r[0]), "=r"(r[1]) : "r"(a));
}
__device__ __forceinline__ void mma16816(float* d, const uint32_t* a, const uint32_t* b){
    asm volatile("mma.sync.aligned.m16n8k16.row.col.f32.bf16.bf16.f32 "
                 "{%0,%1,%2,%3}, {%4,%5,%6,%7}, {%8,%9}, {%0,%1,%2,%3};"
                 : "+f"(d[0]), "+f"(d[1]), "+f"(d[2]), "+f"(d[3])
                 : "r"(a[0]), "r"(a[1]), "r"(a[2]), "r"(a[3]), "r"(b[0]), "r"(b[1]));
}
__device__ __forceinline__ bf bfc(float x){ return __float2bfloat16(x); }

// ------------------------- cast kernels -------------------------
__global__ void castA4_k(const float* __restrict__ i0, const float* __restrict__ i1,
                         const float* __restrict__ i2, const float* __restrict__ i3,
                         bf* __restrict__ out)
{
    const float* in = (blockIdx.y == 0) ? i0 : (blockIdx.y == 1) ? i1 : (blockIdx.y == 2) ? i2 : i3;
    long long i4 = ((long long)blockIdx.x * 256 + threadIdx.x) * 4;
    float4 v = *(const float4*)(in + i4);
    bf* o = out + (long long)blockIdx.y * 2048 * 1024 + i4;
    __nv_bfloat162 a, b;
    a.x = bfc(v.x); a.y = bfc(v.y); b.x = bfc(v.z); b.y = bfc(v.w);
    *(__nv_bfloat162*)(o)     = a;
    *(__nv_bfloat162*)(o + 2) = b;
}
__global__ void castW5_k(const float* __restrict__ i0, const float* __restrict__ i1,
                         const float* __restrict__ i2, const float* __restrict__ i3,
                         const float* __restrict__ i4p, bf* __restrict__ out)
{
    const float* in = (blockIdx.y == 0) ? i0 : (blockIdx.y == 1) ? i1 :
                      (blockIdx.y == 2) ? i2 : (blockIdx.y == 3) ? i3 : i4p;
    long long i4 = ((long long)blockIdx.x * 256 + threadIdx.x) * 4;
    float4 v = *(const float4*)(in + i4);
    bf* o = out + (long long)blockIdx.y * 1024 * 1024 + i4;
    __nv_bfloat162 a, b;
    a.x = bfc(v.x); a.y = bfc(v.y); b.x = bfc(v.z); b.y = bfc(v.w);
    *(__nv_bfloat162*)(o)     = a;
    *(__nv_bfloat162*)(o + 2) = b;
}

// ------------------------- bf16 tensor GEMM, 4-stage cp.async ------------------
// BM=128, BK=32, 8 warps (2m x 4n).
// EPI 6: merged projections (grid.z=4: q[*SCALE], k[+bk], v[+bv], rh) -> g_proj
// EPI 1: content -> sc fp32 (+rwk + tt*cls - INF*(1-mask))
// EPI 2: pos band -> sc RMW shifted (compacted 9-tile grid)
// EPI 3: PV -> av16 bf16
// EPI 4: outproj -> ao fp32 (+bias)
template<int BN, int NT_, bool TRANSB, int EPI>
__global__ __launch_bounds__(256, 2)
void tg(const bf* __restrict__ A, const bf* __restrict__ B,
        const float* __restrict__ bias, const float* __restrict__ bias2,
        float* __restrict__ Cf, bf* __restrict__ Cb,
        int K, int lda, int ldb, int ldc,
        const float* __restrict__ aux, const float* __restrict__ ttd,
        const unsigned char* __restrict__ ttm, const float* __restrict__ clsm,
        const int* __restrict__ amask)
{
    constexpr int NS = 4;
    constexpr int ASZ = 128 * 40;
    constexpr int BSTR = TRANSB ? 40 : (BN + 8);
    constexpr int BROWS = TRANSB ? BN : 32;
    constexpr int BSZ = BROWS * BSTR;
    extern __shared__ __align__(16) bf dyn[];
    bf* Asm = dyn;
    bf* Bsm = dyn + NS * ASZ;

    const int m0 = blockIdx.y * 128;
    int n0 = blockIdx.x * BN;
    const int z = blockIdx.z;
    const int bb = z >> 4, nn = z & 15;
    int zi = 0;

    if (EPI == 6){ zi = z; A += (long long)zi * 2048 * 1024; B += (long long)zi * 1024 * 1024; }
    if (EPI == 1){ A += ((long long)bb * Sc) * 1024 + nn * 64; B += ((long long)bb * Sc) * 1024 + nn * 64;
                   Cf += (long long)z * Sc * Sc; }
    if (EPI == 2){ int ns = 897 - m0; ns = (ns > 0) ? (ns >> 7) : 0; n0 = (ns + blockIdx.x) * BN;
                   A += ((long long)bb * Sc) * 1024 + nn * 64; B += (long long)nn * 64;
                   Cf += (long long)z * Sc * Sc; }
    if (EPI == 3){ A += (long long)z * Sc * 1024; B += (long long)bb * Sc * 1024 + nn * 64; }

    const int t = threadIdx.x, lane = t & 31, warp = t >> 5, wm = warp >> 2, wn = warp & 3;

    float acc[4][NT_][4];
    #pragma unroll
    for (int a = 0; a < 4; ++a)
        #pragma unroll
        for (int b = 0; b < NT_; ++b)
            #pragma unroll
            for (int c = 0; c < 4; ++c) acc[a][b][c] = 0.f;

    auto loadA = [&](int s, int k0){
        #pragma unroll
        for (int q = 0; q < 2; ++q){
            int c = t * 2 + q, row = c >> 2, seg = c & 3;
            cp16(cvta_s(Asm + s * ASZ + row * 40 + seg * 8),
                 A + (long long)(m0 + row) * lda + k0 + seg * 8);
        }
    };
    auto loadB = [&](int s, int k0){
        if (TRANSB){
            #pragma unroll
            for (int q = 0; q < (BN * 4) / 256; ++q){
                int c = t * ((BN * 4) / 256) + q, row = c >> 2, seg = c & 3;
                cp16(cvta_s(Bsm + s * BSZ + row * BSTR + seg * 8),
                     B + (long long)(n0 + row) * ldb + k0 + seg * 8);
            }
        } else {
            constexpr int CPR = BN / 8;
            #pragma unroll
            for (int q = 0; q < (32 * CPR) / 256; ++q){
                int c = t * ((32 * CPR) / 256) + q, row = c / CPR, seg = c % CPR;
                cp16(cvta_s(Bsm + s * BSZ + row * BSTR + seg * 8),
                     B + (long long)(k0 + row) * ldb + n0 + seg * 8);
            }
        }
    };

    const int KT = K / 32;
    loadA(0, 0); loadB(0, 0);
    asm volatile("cp.async.commit_group;");
    if (KT > 1){ loadA(1, 32); loadB(1, 32); }
    asm volatile("cp.async.commit_group;");
    if (KT > 2){ loadA(2, 64); loadB(2, 64); }
    asm volatile("cp.async.commit_group;");

    for (int kt = 0; kt < KT; ++kt){
        asm volatile("cp.async.wait_group 2;");
        __syncthreads();
        int kn = kt + 3;
        if (kn < KT){ loadA(kn & 3, kn * 32); loadB(kn & 3, kn * 32); }
        asm volatile("cp.async.commit_group;");

        const int s = kt & 3;
        const uint32_t aBase = cvta_s(Asm + s * ASZ) + ((wm * 64 + (lane & 15)) * 40) * 2;
        const uint32_t bBase = cvta_s(Bsm + s * BSZ);
        #pragma unroll
        for (int ks = 0; ks < 32; ks += 16){
            uint32_t af[4][4], bfrg[NT_][2];
            #pragma unroll
            for (int mt = 0; mt < 4; ++mt)
                ldm_x4(af[mt], aBase + (mt * 16 * 40 + ks + (lane >> 4) * 8) * 2);
            #pragma unroll
            for (int nt = 0; nt < NT_; ++nt){
                if (TRANSB){
                    int l = lane & 15;
                    ldm_x2(bfrg[nt], bBase + (((wn * (BN / 4) + nt * 8 + (l & 7)) * BSTR + ks + (l >> 3) * 8)) * 2);
                } else {
                    ldm_x2t(bfrg[nt], bBase + (((ks + (lane & 15)) * BSTR + wn * (BN / 4) + nt * 8)) * 2);
                }
            }
            #pragma unroll
            for (int mt = 0; mt < 4; ++mt)
                #pragma unroll
                for (int nt = 0; nt < NT_; ++nt) mma16816(acc[mt][nt], af[mt], bfrg[nt]);
        }
    }

    // ---- epilogue ----
    #pragma unroll
    for (int mt = 0; mt < 4; ++mt)
      #pragma unroll
      for (int r2 = 0; r2 < 2; ++r2){
        const int i = m0 + wm * 64 + mt * 16 + (lane >> 2) + r2 * 8;
        float td0 = 0.f, td1 = 0.f;
        if (EPI == 1){ long long tb = (((long long)bb * Sc + i) * Nc + nn) * 2; td0 = ttd[tb]; td1 = ttd[tb + 1]; }
        #pragma unroll
        for (int nt = 0; nt < NT_; ++nt)
          #pragma unroll
          for (int c2 = 0; c2 < 2; ++c2){
            const int j = n0 + wn * (BN / 4) + nt * 8 + ((lane & 3) << 1) + c2;
            float v = acc[mt][nt][r2 * 2 + c2];
            if (EPI == 6){
                if (zi == 0) v *= SCALE;
                else if (zi == 1) v += bias[j];
                else if (zi == 2) v += bias2[j];
                Cb[(long long)zi * 2048 * 1024 + (long long)i * 1024 + j] = bfc(v);
            } else if (EPI == 1){
                v += aux[(long long)z * Sc + j];
                float tt = ttm[((long long)bb * Sc + i) * Sc + j] ? td1 : td0;
                v += tt * clsm[(long long)i * Sc + j];
                v -= INFV * (1.0f - (float)amask[bb * Sc + j]);
                Cf[(long long)i * ldc + j] = v;
            } else if (EPI == 2){
                const int jj = j + i - Sc;
                if (jj >= 0 && jj < Sc){
                    float pv = (v + aux[nn * Rc + j]) * clsm[(long long)i * Sc + jj];
                    Cf[(long long)i * ldc + jj] += pv;
                }
            } else if (EPI == 3){
                Cb[((long long)bb * Sc + i) * 1024 + nn * 64 + j] = bfc(v);
            } else { // EPI 4
                Cf[(long long)i * ldc + j] = v + bias[j];
            }
          }
      }
}

// ------------------------- small dot kernels -------------------------
__global__ void rwk_k(const bf* __restrict__ k16, const float* __restrict__ rwb, float* __restrict__ rwk){
    int gw = (blockIdx.x * blockDim.x + threadIdx.x) >> 5;
    int lane = threadIdx.x & 31;
    if (gw >= Bc * Nc * Sc) return;
    int zz = gw >> 10, j = gw & (Sc - 1);
    int b = zz >> 4, n = zz & 15;
    const bf* kp = k16 + ((long long)(b * 1024 + j)) * 1024 + n * 64;
    float d = 0.f;
    #pragma unroll
    for (int h = lane; h < Hc; h += 32) d += rwb[n * Hc + h] * __bfloat162float(kp[h]);
    #pragma unroll
    for (int o = 16; o; o >>= 1) d += __shfl_down_sync(0xffffffffu, d, o);
    if (lane == 0) rwk[gw] = d * SCALE;
}
__global__ void rrt_k(const bf* __restrict__ rh16, const float* __restrict__ rrb, float* __restrict__ rrt){
    int gw = (blockIdx.x * blockDim.x + threadIdx.x) >> 5;
    int lane = threadIdx.x & 31;
    if (gw >= Nc * Rc) return;
    int n = gw >> 11, tt = gw & (Rc - 1);
    const bf* rp = rh16 + (long long)tt * 1024 + n * 64;
    float d = 0.f;
    #pragma unroll
    for (int h = lane; h < Hc; h += 32) d += rrb[n * Hc + h] * __bfloat162float(rp[h]);
    #pragma unroll
    for (int o = 16; o; o >>= 1) d += __shfl_down_sync(0xffffffffu, d, o);
    if (lane == 0) rrt[gw] = d * SCALE;
}
__global__ void ttd_k(const bf* __restrict__ q16, const float* __restrict__ seg,
                      const float* __restrict__ rsb, float* __restrict__ ttd){
    int gw = (blockIdx.x * blockDim.x + threadIdx.x) >> 5;
    int lane = threadIdx.x & 31;
    if (gw >= Bc * Sc * Nc) return;
    int n = gw & 15;
    long long bi = gw >> 4;
    const bf* qp = q16 + bi * 1024 + n * 64;
    float d0 = 0.f, d1 = 0.f, s0 = 0.f, s1 = 0.f;
    #pragma unroll
    for (int h = lane; h < Hc; h += 32){
        float e0 = seg[n * Hc + h], e1 = seg[Nc * Hc + n * Hc + h];
        float qv = __bfloat162float(qp[h]), rv = rsb[n * Hc + h];
        d0 += qv * e0; d1 += qv * e1; s0 += rv * e0; s1 += rv * e1;
    }
    #pragma unroll
    for (int o = 16; o; o >>= 1){
        d0 += __shfl_down_sync(0xffffffffu, d0, o);
        d1 += __shfl_down_sync(0xffffffffu, d1, o);
        s0 += __shfl_down_sync(0xffffffffu, s0, o);
        s1 += __shfl_down_sync(0xffffffffu, s1, o);
    }
    if (lane == 0){ ttd[2 * gw] = d0 + SCALE * s0; ttd[2 * gw + 1] = d1 + SCALE * s1; }
}

// ------------------------- softmax -> bf16 probs -------------------------
__global__ void softmax_k(const float* __restrict__ sc, bf* __restrict__ p16){
    __shared__ float red[256];
    long long row = blockIdx.x;
    const float* p = sc + row * Sc;
    bf* o = p16 + row * 1024;
    int t = threadIdx.x;
    float v[4]; float m = -3.4e38f;
    #pragma unroll
    for (int u = 0; u < 4; ++u){ v[u] = p[t + u * 256]; m = fmaxf(m, v[u]); }
    red[t] = m; __syncthreads();
    #pragma unroll
    for (int s = 128; s; s >>= 1){ if (t < s) red[t] = fmaxf(red[t], red[t + s]); __syncthreads(); }
    m = red[0]; __syncthreads();
    float sum = 0.f;
    #pragma unroll
    for (int u = 0; u < 4; ++u){ v[u] = expf(v[u] - m); sum += v[u]; }
    red[t] = sum; __syncthreads();
    #pragma unroll
    for (int s = 128; s; s >>= 1){ if (t < s) red[t] += red[t + s]; __syncthreads(); }
    float inv = 1.0f / red[0];
    #pragma unroll
    for (int u = 0; u < 4; ++u) o[t + u * 256] = bfc(v[u] * inv);
}

// ------------------------- residual + LayerNorm -------------------------
__global__ void ln_k(const float* __restrict__ query, const float* __restrict__ ao,
                     const float* __restrict__ gamma, const float* __restrict__ beta,
                     float* __restrict__ out){
    __shared__ float red[256];
    long long base = (long long)blockIdx.x * Dc;
    int t = threadIdx.x;
    float x[4]; float s = 0.f;
    #pragma unroll
    for (int u = 0; u < 4; ++u){ x[u] = query[base + t + u * 256] + ao[base + t + u * 256]; s += x[u]; }
    red[t] = s; __syncthreads();
    #pragma unroll
    for (int o = 128; o; o >>= 1){ if (t < o) red[t] += red[t + o]; __syncthreads(); }
    float mu = red[0] * (1.0f / Dc); __syncthreads();
    float s2 = 0.f;
    #pragma unroll
    for (int u = 0; u < 4; ++u){ float d = x[u] - mu; s2 += d * d; }
    red[t] = s2; __syncthreads();
    #pragma unroll
    for (int o = 128; o; o >>= 1){ if (t < o) red[t] += red[t + o]; __syncthreads(); }
    float inv = rsqrtf(red[0] * (1.0f / Dc) + EPSV);
    #pragma unroll
    for (int u = 0; u < 4; ++u){
        int c = t + u * 256;
        out[base + c] = (x[u] - mu) * inv * gamma[c] + beta[c];
    }
}

// ------------------------- driver -------------------------
extern "C" void kernel_launch(void* const* d_in, const int* in_sizes, int n_in,
                              void* d_out, int out_size)
{
    const float* query = (const float*)d_in[0];
    const float* key   = (const float*)d_in[1];
    const float* value = (const float*)d_in[2];
    const float* r     = (const float*)d_in[3];
    const float* clsm  = (const float*)d_in[4];
    const float* Wq    = (const float*)d_in[5];
    const float* Wk    = (const float*)d_in[6];
    const float* bk    = (const float*)d_in[7];
    const float* Wv    = (const float*)d_in[8];
    const float* bv    = (const float*)d_in[9];
    const float* Wo    = (const float*)d_in[10];
    const float* bo    = (const float*)d_in[11];
    const float* rwb   = (const float*)d_in[12];
    const float* rrb   = (const float*)d_in[13];
    const float* rkern = (const float*)d_in[14];
    const float* rsb   = (const float*)d_in[15];
    const float* seg   = (const float*)d_in[16];
    const float* gamma = (const float*)d_in[17];
    const float* beta  = (const float*)d_in[18];
    const unsigned char* ttm = (const unsigned char*)d_in[19];
    const int*   amask = (const int*)d_in[20];
    float* out = (float*)d_out;

    bf *in16, *w16, *proj, *p16, *av16;
    float *sc, *ao, *rwk, *rrt, *ttd;
    cudaGetSymbolAddress((void**)&in16, g_in16);
    cudaGetSymbolAddress((void**)&w16,  g_w16);
    cudaGetSymbolAddress((void**)&proj, g_proj);
    cudaGetSymbolAddress((void**)&p16,  g_p16);
    cudaGetSymbolAddress((void**)&av16, g_av16);
    cudaGetSymbolAddress((void**)&sc,   g_sc);
    cudaGetSymbolAddress((void**)&ao,   g_ao);
    cudaGetSymbolAddress((void**)&rwk,  g_rwk);
    cudaGetSymbolAddress((void**)&rrt,  g_rrt);
    cudaGetSymbolAddress((void**)&ttd,  g_ttd);

    bf* q16  = proj;
    bf* k16  = proj + 1LL * 2048 * 1024;
    bf* v16  = proj + 2LL * 2048 * 1024;
    bf* rh16 = proj + 3LL * 2048 * 1024;

    auto k6 = tg<128, 4, false, 6>;
    auto k1 = tg<128, 4, true,  1>;
    auto k2 = tg<128, 4, true,  2>;
    auto k3 = tg<64,  2, false, 3>;
    auto k4 = tg<128, 4, false, 4>;
    cudaFuncSetAttribute(k6, cudaFuncAttributeMaxDynamicSharedMemorySize, 75776);
    cudaFuncSetAttribute(k1, cudaFuncAttributeMaxDynamicSharedMemorySize, 81920);
    cudaFuncSetAttribute(k2, cudaFuncAttributeMaxDynamicSharedMemorySize, 81920);
    cudaFuncSetAttribute(k3, cudaFuncAttributeMaxDynamicSharedMemorySize, 59392);
    cudaFuncSetAttribute(k4, cudaFuncAttributeMaxDynamicSharedMemorySize, 75776);

    // 0) casts
    castA4_k<<<dim3(2048, 4), 256>>>(query, key, value, r, in16);
    castW5_k<<<dim3(1024, 5), 256>>>(Wq, Wk, Wv, rkern, Wo, w16);

    // 1) merged projections (grid.z: q,k,v,rh), K=1024
    k6<<<dim3(8, 16, 4), 256, 75776>>>(in16, w16, bk, bv, nullptr, proj,
        1024, 1024, 1024, 0, nullptr, nullptr, nullptr, nullptr, nullptr);

    // 2) tiny bias-dot tables
    rwk_k<<<4096, 256>>>(k16, rwb, rwk);
    rrt_k<<<4096, 256>>>(rh16, rrb, rrt);
    ttd_k<<<4096, 256>>>(q16, seg, rsb, ttd);

    // 3) content scores fused (per bn: 1024x1024, K=64)
    k1<<<dim3(8, 8, Bc * Nc), 256, 81920>>>(q16, k16, nullptr, nullptr, sc, nullptr,
        64, 1024, 1024, 1024, rwk, ttd, ttm, clsm, amask);

    // 4) pos band RMW (per bn: 1024 x 9*128 band tiles, K=64)
    k2<<<dim3(9, 8, Bc * Nc), 256, 81920>>>(q16, rh16, nullptr, nullptr, sc, nullptr,
        64, 1024, 1024, 1024, rrt, nullptr, nullptr, clsm, nullptr);

    // 5) softmax -> bf16 probs
    softmax_k<<<Bc * Nc * Sc, 256>>>(sc, p16);

    // 6) PV (per bn: 1024x64, K=1024) -> av16
    k3<<<dim3(1, 8, Bc * Nc), 256, 59392>>>(p16, v16, nullptr, nullptr, nullptr, av16,
        1024, 1024, 1024, 0, nullptr, nullptr, nullptr, nullptr, nullptr);

    // 7) output projection (2048x1024, K=1024) + bias -> ao fp32
    k4<<<dim3(8, 16, 1), 256, 75776>>>(av16, w16 + 4LL * 1024 * 1024, bo, nullptr, ao, nullptr,
        1024, 1024, 1024, 1024, nullptr, nullptr, nullptr, nullptr, nullptr);

    // 8) residual + LayerNorm
    ln_k<<<Bc * Sc, 256>>>(query, ao, gamma, beta, out);

    (void)in_sizes; (void)n_in; (void)out_size;
}

// round 5
// speedup vs baseline: 5.0625x; 1.9542x over previous
#include <cuda_runtime.h>
#include <cuda_bf16.h>
#include <math.h>
#include <stdint.h>

#define Bc 2
#define Sc 1024
#define Dc 1024
#define Nc 16
#define Hc 64
#define NHc 1024
#define Rc 2048
#define SCALE 0.125f
#define INFV 1000000.0f
#define EPSV 1e-9f

typedef __nv_bfloat16 bf;

// ------------------------- scratch -------------------------
__device__ bf g_in16[4 * 2048 * 1024];
__device__ bf g_w16 [5 * 1024 * 1024];
__device__ bf g_proj[4 * 2048 * 1024];
__device__ float g_sc[(long long)32 * 1024 * 1024];
__device__ bf g_p16[(long long)32 * 1024 * 1024];
__device__ bf g_av16[2048 * 1024];
__device__ float g_ao[2048 * 1024];
__device__ float g_rwk[32 * 1024];
__device__ float g_rrt[16 * 2048];
__device__ float g_ttd[2048 * 16 * 2];

// ------------------------- helpers -------------------------
__device__ __forceinline__ uint32_t cvta_s(const void* p){ return (uint32_t)__cvta_generic_to_shared(p); }
__device__ __forceinline__ void cp16(uint32_t d, const void* s){
    asm volatile("cp.async.cg.shared.global [%0], [%1], 16;" :: "r"(d), "l"(s));
}
__device__ __forceinline__ void ldm_x4(uint32_t* r, uint32_t a){
    asm volatile("ldmatrix.sync.aligned.m8n8.x4.shared.b16 {%0,%1,%2,%3}, [%4];"
                 : "=r"(r[0]), "=r"(r[1]), "=r"(r[2]), "=r"(r[3]) : "r"(a));
}
__device__ __forceinline__ void ldm_x2t(uint32_t* r, uint32_t a){
    asm volatile("ldmatrix.sync.aligned.m8n8.x2.trans.shared.b16 {%0,%1}, [%2];"
                 : "=r"(r[0]), "=r"(r[1]) : "r"(a));
}
__device__ __forceinline__ void ldm_x2(uint32_t* r, uint32_t a){
    asm volatile("ldmatrix.sync.aligned.m8n8.x2.shared.b16 {%0,%1}, [%2];"
                 : "=r"(r[0]), "=r"(r[1]) : "r"(a));
}
__device__ __forceinline__ void mma16816(float* d, const uint32_t* a, const uint32_t* b){
    asm volatile("mma.sync.aligned.m16n8k16.row.col.f32.bf16.bf16.f32 "
                 "{%0,%1,%2,%3}, {%4,%5,%6,%7}, {%8,%9}, {%0,%1,%2,%3};"
                 : "+f"(d[0]), "+f"(d[1]), "+f"(d[2]), "+f"(d[3])
                 : "r"(a[0]), "r"(a[1]), "r"(a[2]), "r"(a[3]), "r"(b[0]), "r"(b[1]));
}
__device__ __forceinline__ bf bfc(float x){ return __float2bfloat16(x); }

// ------------------------- cast kernels -------------------------
__global__ void castA4_k(const float* __restrict__ i0, const float* __restrict__ i1,
                         const float* __restrict__ i2, const float* __restrict__ i3,
                         bf* __restrict__ out)
{
    const float* in = (blockIdx.y == 0) ? i0 : (blockIdx.y == 1) ? i1 : (blockIdx.y == 2) ? i2 : i3;
    long long i4 = ((long long)blockIdx.x * 256 + threadIdx.x) * 4;
    float4 v = *(const float4*)(in + i4);
    bf* o = out + (long long)blockIdx.y * 2048 * 1024 + i4;
    __nv_bfloat162 a, b;
    a.x = bfc(v.x); a.y = bfc(v.y); b.x = bfc(v.z); b.y = bfc(v.w);
    *(__nv_bfloat162*)(o)     = a;
    *(__nv_bfloat162*)(o + 2) = b;
}
__global__ void castW5_k(const float* __restrict__ i0, const float* __restrict__ i1,
                         const float* __restrict__ i2, const float* __restrict__ i3,
                         const float* __restrict__ i4p, bf* __restrict__ out)
{
    const float* in = (blockIdx.y == 0) ? i0 : (blockIdx.y == 1) ? i1 :
                      (blockIdx.y == 2) ? i2 : (blockIdx.y == 3) ? i3 : i4p;
    long long i4 = ((long long)blockIdx.x * 256 + threadIdx.x) * 4;
    float4 v = *(const float4*)(in + i4);
    bf* o = out + (long long)blockIdx.y * 1024 * 1024 + i4;
    __nv_bfloat162 a, b;
    a.x = bfc(v.x); a.y = bfc(v.y); b.x = bfc(v.z); b.y = bfc(v.w);
    *(__nv_bfloat162*)(o)     = a;
    *(__nv_bfloat162*)(o + 2) = b;
}

// ------------------------- generic bf16 GEMM (proj / PV / outproj) ------------
template<int BN, int NT_, bool TRANSB, int EPI>
__global__ __launch_bounds__(256, 2)
void tg(const bf* __restrict__ A, const bf* __restrict__ B,
        const float* __restrict__ bias, const float* __restrict__ bias2,
        float* __restrict__ Cf, bf* __restrict__ Cb,
        int K, int lda, int ldb, int ldc)
{
    constexpr int NS = 4;
    constexpr int ASZ = 128 * 40;
    constexpr int BSTR = TRANSB ? 40 : (BN + 8);
    constexpr int BROWS = TRANSB ? BN : 32;
    constexpr int BSZ = BROWS * BSTR;
    extern __shared__ __align__(16) bf dyn[];
    bf* Asm = dyn;
    bf* Bsm = dyn + NS * ASZ;

    const int m0 = blockIdx.y * 128;
    int n0 = blockIdx.x * BN;
    const int z = blockIdx.z;
    const int bb = z >> 4, nn = z & 15;
    int zi = 0;

    if (EPI == 6){ zi = z; A += (long long)zi * 2048 * 1024; B += (long long)zi * 1024 * 1024; }
    if (EPI == 3){ A += (long long)z * Sc * 1024; B += (long long)bb * Sc * 1024 + nn * 64; }

    const int t = threadIdx.x, lane = t & 31, warp = t >> 5, wm = warp >> 2, wn = warp & 3;

    float acc[4][NT_][4];
    #pragma unroll
    for (int a = 0; a < 4; ++a)
        #pragma unroll
        for (int b = 0; b < NT_; ++b)
            #pragma unroll
            for (int c = 0; c < 4; ++c) acc[a][b][c] = 0.f;

    auto loadA = [&](int s, int k0){
        #pragma unroll
        for (int q = 0; q < 2; ++q){
            int c = t * 2 + q, row = c >> 2, seg = c & 3;
            cp16(cvta_s(Asm + s * ASZ + row * 40 + seg * 8),
                 A + (long long)(m0 + row) * lda + k0 + seg * 8);
        }
    };
    auto loadB = [&](int s, int k0){
        if (TRANSB){
            #pragma unroll
            for (int q = 0; q < (BN * 4) / 256; ++q){
                int c = t * ((BN * 4) / 256) + q, row = c >> 2, seg = c & 3;
                cp16(cvta_s(Bsm + s * BSZ + row * BSTR + seg * 8),
                     B + (long long)(n0 + row) * ldb + k0 + seg * 8);
            }
        } else {
            constexpr int CPR = BN / 8;
            #pragma unroll
            for (int q = 0; q < (32 * CPR) / 256; ++q){
                int c = t * ((32 * CPR) / 256) + q, row = c / CPR, seg = c % CPR;
                cp16(cvta_s(Bsm + s * BSZ + row * BSTR + seg * 8),
                     B + (long long)(k0 + row) * ldb + n0 + seg * 8);
            }
        }
    };

    const int KT = K / 32;
    loadA(0, 0); loadB(0, 0);
    asm volatile("cp.async.commit_group;");
    if (KT > 1){ loadA(1, 32); loadB(1, 32); }
    asm volatile("cp.async.commit_group;");
    if (KT > 2){ loadA(2, 64); loadB(2, 64); }
    asm volatile("cp.async.commit_group;");

    for (int kt = 0; kt < KT; ++kt){
        asm volatile("cp.async.wait_group 2;");
        __syncthreads();
        int kn = kt + 3;
        if (kn < KT){ loadA(kn & 3, kn * 32); loadB(kn & 3, kn * 32); }
        asm volatile("cp.async.commit_group;");

        const int s = kt & 3;
        const uint32_t aBase = cvta_s(Asm + s * ASZ) + ((wm * 64 + (lane & 15)) * 40) * 2;
        const uint32_t bBase = cvta_s(Bsm + s * BSZ);
        #pragma unroll
        for (int ks = 0; ks < 32; ks += 16){
            uint32_t af[4][4], bfrg[NT_][2];
            #pragma unroll
            for (int mt = 0; mt < 4; ++mt)
                ldm_x4(af[mt], aBase + (mt * 16 * 40 + ks + (lane >> 4) * 8) * 2);
            #pragma unroll
            for (int nt = 0; nt < NT_; ++nt){
                if (TRANSB){
                    int l = lane & 15;
                    ldm_x2(bfrg[nt], bBase + (((wn * (BN / 4) + nt * 8 + (l & 7)) * BSTR + ks + (l >> 3) * 8)) * 2);
                } else {
                    ldm_x2t(bfrg[nt], bBase + (((ks + (lane & 15)) * BSTR + wn * (BN / 4) + nt * 8)) * 2);
                }
            }
            #pragma unroll
            for (int mt = 0; mt < 4; ++mt)
                #pragma unroll
                for (int nt = 0; nt < NT_; ++nt) mma16816(acc[mt][nt], af[mt], bfrg[nt]);
        }
    }

    #pragma unroll
    for (int mt = 0; mt < 4; ++mt)
      #pragma unroll
      for (int r2 = 0; r2 < 2; ++r2){
        const int i = m0 + wm * 64 + mt * 16 + (lane >> 2) + r2 * 8;
        #pragma unroll
        for (int nt = 0; nt < NT_; ++nt)
          #pragma unroll
          for (int c2 = 0; c2 < 2; ++c2){
            const int j = n0 + wn * (BN / 4) + nt * 8 + ((lane & 3) << 1) + c2;
            float v = acc[mt][nt][r2 * 2 + c2];
            if (EPI == 6){
                if (zi == 0) v *= SCALE;
                else if (zi == 1) v += bias[j];
                else if (zi == 2) v += bias2[j];
                Cb[(long long)zi * 2048 * 1024 + (long long)i * 1024 + j] = bfc(v);
            } else if (EPI == 3){
                Cb[((long long)bb * Sc + i) * 1024 + nn * 64 + j] = bfc(v);
            } else { // EPI 4
                Cf[(long long)i * ldc + j] = v + bias[j];
            }
          }
      }
}

// ------------------------- fused content+pos score kernel --------------------
// grid (8 j-tiles, 8 i-tiles, 32 bn). 256 thr, warps 2(m)x4(n).
// sc[i,j] = C + rwk[j] + (P[i,1024+j-i]+rrt)*cls + tt*cls - INF*(1-mask)
#define QS_OFF  0
#define KS_OFF  (128*72)
#define RHS_OFF (2*128*72)
#define PS_OFF  (4*128*72)      // in bf16 elements; P is fp32 region after this
#define PSTR 264

__global__ __launch_bounds__(256)
void score_k(const bf* __restrict__ q16, const bf* __restrict__ k16,
             const bf* __restrict__ rh16, float* __restrict__ sc,
             const float* __restrict__ rwk, const float* __restrict__ rrt,
             const float* __restrict__ ttd, const unsigned char* __restrict__ ttm,
             const float* __restrict__ clsm, const int* __restrict__ amask)
{
    extern __shared__ __align__(16) bf dyn[];
    bf* qs  = dyn + QS_OFF;     // [128][72]
    bf* ks_ = dyn + KS_OFF;     // [128][72]
    bf* rhs = dyn + RHS_OFF;    // [256][72]
    float* Ps = (float*)(dyn + PS_OFF);  // [128][PSTR]

    const int j0 = blockIdx.x * 128, i0 = blockIdx.y * 128, z = blockIdx.z;
    const int bb = z >> 4, nn = z & 15;
    const int tb0 = 1024 + j0 - i0 - 128;   // in [0,1792]

    const bf* qg  = q16  + ((long long)(bb * 1024 + i0)) * 1024 + nn * 64;
    const bf* kg  = k16  + ((long long)(bb * 1024 + j0)) * 1024 + nn * 64;
    const bf* rhg = rh16 + (long long)tb0 * 1024 + nn * 64;

    const int t = threadIdx.x, lane = t & 31, warp = t >> 5, wm = warp >> 2, wn = warp & 3;

    // stage q, k (128x64) and rh (256x64)
    #pragma unroll
    for (int qq = 0; qq < 4; ++qq){
        int c = qq * 256 + t, row = c >> 3, seg = c & 7;
        cp16(cvta_s(qs  + row * 72 + seg * 8), qg + (long long)row * 1024 + seg * 8);
    }
    #pragma unroll
    for (int qq = 0; qq < 4; ++qq){
        int c = qq * 256 + t, row = c >> 3, seg = c & 7;
        cp16(cvta_s(ks_ + row * 72 + seg * 8), kg + (long long)row * 1024 + seg * 8);
    }
    #pragma unroll
    for (int qq = 0; qq < 8; ++qq){
        int c = qq * 256 + t, row = c >> 3, seg = c & 7;
        cp16(cvta_s(rhs + row * 72 + seg * 8), rhg + (long long)row * 1024 + seg * 8);
    }
    asm volatile("cp.async.commit_group;");
    asm volatile("cp.async.wait_group 0;");
    __syncthreads();

    const uint32_t aBase = cvta_s(qs) + ((wm * 64 + (lane & 15)) * 72 + (lane >> 4) * 8) * 2;
    const uint32_t kBase = cvta_s(ks_);
    const uint32_t rBase = cvta_s(rhs);
    const int l = lane & 15;

    // ---- content: C = q @ k^T, K=64 ----
    float accC[4][4][4];
    #pragma unroll
    for (int a = 0; a < 4; ++a)
        #pragma unroll
        for (int b = 0; b < 4; ++b)
            #pragma unroll
            for (int c = 0; c < 4; ++c) accC[a][b][c] = 0.f;

    #pragma unroll
    for (int ksx = 0; ksx < 64; ksx += 16){
        uint32_t af[4][4], bfrg[4][2];
        #pragma unroll
        for (int mt = 0; mt < 4; ++mt) ldm_x4(af[mt], aBase + (mt * 16 * 72 + ksx) * 2);
        #pragma unroll
        for (int nt = 0; nt < 4; ++nt)
            ldm_x2(bfrg[nt], kBase + ((wn * 32 + nt * 8 + (l & 7)) * 72 + ksx + (l >> 3) * 8) * 2);
        #pragma unroll
        for (int mt = 0; mt < 4; ++mt)
            #pragma unroll
            for (int nt = 0; nt < 4; ++nt) mma16816(accC[mt][nt], af[mt], bfrg[nt]);
    }

    // ---- pos: P = q @ rh^T (128x256 in two halves), +rrt, to smem ----
    #pragma unroll
    for (int ph = 0; ph < 2; ++ph){
        float accP[4][4][4];
        #pragma unroll
        for (int a = 0; a < 4; ++a)
            #pragma unroll
            for (int b = 0; b < 4; ++b)
                #pragma unroll
                for (int c = 0; c < 4; ++c) accP[a][b][c] = 0.f;
        #pragma unroll
        for (int ksx = 0; ksx < 64; ksx += 16){
            uint32_t af[4][4], bfrg[4][2];
            #pragma unroll
            for (int mt = 0; mt < 4; ++mt) ldm_x4(af[mt], aBase + (mt * 16 * 72 + ksx) * 2);
            #pragma unroll
            for (int nt = 0; nt < 4; ++nt)
                ldm_x2(bfrg[nt], rBase + ((ph * 128 + wn * 32 + nt * 8 + (l & 7)) * 72 + ksx + (l >> 3) * 8) * 2);
            #pragma unroll
            for (int mt = 0; mt < 4; ++mt)
                #pragma unroll
                for (int nt = 0; nt < 4; ++nt) mma16816(accP[mt][nt], af[mt], bfrg[nt]);
        }
        // store P half (+rrt) to smem
        #pragma unroll
        for (int mt = 0; mt < 4; ++mt)
            #pragma unroll
            for (int r2 = 0; r2 < 2; ++r2){
                int ir = wm * 64 + mt * 16 + (lane >> 2) + r2 * 8;
                #pragma unroll
                for (int nt = 0; nt < 4; ++nt)
                    #pragma unroll
                    for (int c2 = 0; c2 < 2; ++c2){
                        int col = ph * 128 + wn * 32 + nt * 8 + ((lane & 3) << 1) + c2;
                        Ps[ir * PSTR + col] = accP[mt][nt][r2 * 2 + c2] + rrt[nn * Rc + tb0 + col];
                    }
            }
    }
    __syncthreads();

    // ---- epilogue ----
    #pragma unroll
    for (int mt = 0; mt < 4; ++mt)
      #pragma unroll
      for (int r2 = 0; r2 < 2; ++r2){
        const int il = wm * 64 + mt * 16 + (lane >> 2) + r2 * 8;
        const int i = i0 + il;
        long long tb = (((long long)bb * Sc + i) * Nc + nn) * 2;
        float td0 = ttd[tb], td1 = ttd[tb + 1];
        #pragma unroll
        for (int nt = 0; nt < 4; ++nt)
          #pragma unroll
          for (int c2 = 0; c2 < 2; ++c2){
            const int dj = wn * 32 + nt * 8 + ((lane & 3) << 1) + c2;
            const int j = j0 + dj;
            float pval = Ps[il * PSTR + 128 + dj - il];
            float tt = ttm[((long long)bb * Sc + i) * Sc + j] ? td1 : td0;
            float cl = clsm[(long long)i * Sc + j];
            float v = accC[mt][nt][r2 * 2 + c2] + rwk[(long long)z * Sc + j]
                    + (pval + tt) * cl
                    - INFV * (1.0f - (float)amask[bb * Sc + j]);
            sc[(long long)z * Sc * Sc + (long long)i * Sc + j] = v;
          }
      }
}

// ------------------------- merged dot kernels -------------------------
__global__ void dots_k(const bf* __restrict__ q16, const bf* __restrict__ k16,
                       const bf* __restrict__ rh16,
                       const float* __restrict__ rwb, const float* __restrict__ rrb,
                       const float* __restrict__ rsb, const float* __restrict__ seg,
                       float* __restrict__ rwk, float* __restrict__ rrt, float* __restrict__ ttd)
{
    int gw = (blockIdx.x * blockDim.x + threadIdx.x) >> 5;
    int lane = threadIdx.x & 31;
    if (blockIdx.y == 0){
        int zz = gw >> 10, j = gw & (Sc - 1);
        int b = zz >> 4, n = zz & 15;
        const bf* kp = k16 + ((long long)(b * 1024 + j)) * 1024 + n * 64;
        float d = 0.f;
        #pragma unroll
        for (int h = lane; h < Hc; h += 32) d += rwb[n * Hc + h] * __bfloat162float(kp[h]);
        #pragma unroll
        for (int o = 16; o; o >>= 1) d += __shfl_down_sync(0xffffffffu, d, o);
        if (lane == 0) rwk[gw] = d * SCALE;
    } else if (blockIdx.y == 1){
        int n = gw >> 11, tt2 = gw & (Rc - 1);
        const bf* rp = rh16 + (long long)tt2 * 1024 + n * 64;
        float d = 0.f;
        #pragma unroll
        for (int h = lane; h < Hc; h += 32) d += rrb[n * Hc + h] * __bfloat162float(rp[h]);
        #pragma unroll
        for (int o = 16; o; o >>= 1) d += __shfl_down_sync(0xffffffffu, d, o);
        if (lane == 0) rrt[gw] = d * SCALE;
    } else {
        int n = gw & 15;
        long long bi = gw >> 4;
        const bf* qp = q16 + bi * 1024 + n * 64;
        float d0 = 0.f, d1 = 0.f, s0 = 0.f, s1 = 0.f;
        #pragma unroll
        for (int h = lane; h < Hc; h += 32){
            float e0 = seg[n * Hc + h], e1 = seg[Nc * Hc + n * Hc + h];
            float qv = __bfloat162float(qp[h]), rv = rsb[n * Hc + h];
            d0 += qv * e0; d1 += qv * e1; s0 += rv * e0; s1 += rv * e1;
        }
        #pragma unroll
        for (int o = 16; o; o >>= 1){
            d0 += __shfl_down_sync(0xffffffffu, d0, o);
            d1 += __shfl_down_sync(0xffffffffu, d1, o);
            s0 += __shfl_down_sync(0xffffffffu, s0, o);
            s1 += __shfl_down_sync(0xffffffffu, s1, o);
        }
        if (lane == 0){ ttd[2 * gw] = d0 + SCALE * s0; ttd[2 * gw + 1] = d1 + SCALE * s1; }
    }
}

// ------------------------- softmax -> bf16 probs -------------------------
__global__ void softmax_k(const float* __restrict__ sc, bf* __restrict__ p16){
    __shared__ float red[256];
    long long row = blockIdx.x;
    const float* p = sc + row * Sc;
    bf* o = p16 + row * 1024;
    int t = threadIdx.x;
    float v[4]; float m = -3.4e38f;
    #pragma unroll
    for (int u = 0; u < 4; ++u){ v[u] = p[t + u * 256]; m = fmaxf(m, v[u]); }
    red[t] = m; __syncthreads();
    #pragma unroll
    for (int s = 128; s; s >>= 1){ if (t < s) red[t] = fmaxf(red[t], red[t + s]); __syncthreads(); }
    m = red[0]; __syncthreads();
    float sum = 0.f;
    #pragma unroll
    for (int u = 0; u < 4; ++u){ v[u] = expf(v[u] - m); sum += v[u]; }
    red[t] = sum; __syncthreads();
    #pragma unroll
    for (int s = 128; s; s >>= 1){ if (t < s) red[t] += red[t + s]; __syncthreads(); }
    float inv = 1.0f / red[0];
    #pragma unroll
    for (int u = 0; u < 4; ++u) o[t + u * 256] = bfc(v[u] * inv);
}

// ------------------------- residual + LayerNorm -------------------------
__global__ void ln_k(const float* __restrict__ query, const float* __restrict__ ao,
                     const float* __restrict__ gamma, const float* __restrict__ beta,
                     float* __restrict__ out){
    __shared__ float red[256];
    long long base = (long long)blockIdx.x * Dc;
    int t = threadIdx.x;
    float x[4]; float s = 0.f;
    #pragma unroll
    for (int u = 0; u < 4; ++u){ x[u] = query[base + t + u * 256] + ao[base + t + u * 256]; s += x[u]; }
    red[t] = s; __syncthreads();
    #pragma unroll
    for (int o = 128; o; o >>= 1){ if (t < o) red[t] += red[t + o]; __syncthreads(); }
    float mu = red[0] * (1.0f / Dc); __syncthreads();
    float s2 = 0.f;
    #pragma unroll
    for (int u = 0; u < 4; ++u){ float d = x[u] - mu; s2 += d * d; }
    red[t] = s2; __syncthreads();
    #pragma unroll
    for (int o = 128; o; o >>= 1){ if (t < o) red[t] += red[t + o]; __syncthreads(); }
    float inv = rsqrtf(red[0] * (1.0f / Dc) + EPSV);
    #pragma unroll
    for (int u = 0; u < 4; ++u){
        int c = t + u * 256;
        out[base + c] = (x[u] - mu) * inv * gamma[c] + beta[c];
    }
}

// ------------------------- driver -------------------------
extern "C" void kernel_launch(void* const* d_in, const int* in_sizes, int n_in,
                              void* d_out, int out_size)
{
    const float* query = (const float*)d_in[0];
    const float* key   = (const float*)d_in[1];
    const float* value = (const float*)d_in[2];
    const float* r     = (const float*)d_in[3];
    const float* clsm  = (const float*)d_in[4];
    const float* Wq    = (const float*)d_in[5];
    const float* Wk    = (const float*)d_in[6];
    const float* bk    = (const float*)d_in[7];
    const float* Wv    = (const float*)d_in[8];
    const float* bv    = (const float*)d_in[9];
    const float* Wo    = (const float*)d_in[10];
    const float* bo    = (const float*)d_in[11];
    const float* rwb   = (const float*)d_in[12];
    const float* rrb   = (const float*)d_in[13];
    const float* rkern = (const float*)d_in[14];
    const float* rsb   = (const float*)d_in[15];
    const float* seg   = (const float*)d_in[16];
    const float* gamma = (const float*)d_in[17];
    const float* beta  = (const float*)d_in[18];
    const unsigned char* ttm = (const unsigned char*)d_in[19];
    const int*   amask = (const int*)d_in[20];
    float* out = (float*)d_out;

    bf *in16, *w16, *proj, *p16, *av16;
    float *sc, *ao, *rwk, *rrt, *ttd;
    cudaGetSymbolAddress((void**)&in16, g_in16);
    cudaGetSymbolAddress((void**)&w16,  g_w16);
    cudaGetSymbolAddress((void**)&proj, g_proj);
    cudaGetSymbolAddress((void**)&p16,  g_p16);
    cudaGetSymbolAddress((void**)&av16, g_av16);
    cudaGetSymbolAddress((void**)&sc,   g_sc);
    cudaGetSymbolAddress((void**)&ao,   g_ao);
    cudaGetSymbolAddress((void**)&rwk,  g_rwk);
    cudaGetSymbolAddress((void**)&rrt,  g_rrt);
    cudaGetSymbolAddress((void**)&ttd,  g_ttd);

    bf* q16  = proj;
    bf* k16  = proj + 1LL * 2048 * 1024;
    bf* v16  = proj + 2LL * 2048 * 1024;
    bf* rh16 = proj + 3LL * 2048 * 1024;

    auto k6 = tg<128, 4, false, 6>;
    auto k3 = tg<64,  2, false, 3>;
    auto k4 = tg<128, 4, false, 4>;
    cudaFuncSetAttribute(k6, cudaFuncAttributeMaxDynamicSharedMemorySize, 75776);
    cudaFuncSetAttribute(k3, cudaFuncAttributeMaxDynamicSharedMemorySize, 59392);
    cudaFuncSetAttribute(k4, cudaFuncAttributeMaxDynamicSharedMemorySize, 75776);
    cudaFuncSetAttribute(score_k, cudaFuncAttributeMaxDynamicSharedMemorySize, 208896);

    // 0) casts
    castA4_k<<<dim3(2048, 4), 256>>>(query, key, value, r, in16);
    castW5_k<<<dim3(1024, 5), 256>>>(Wq, Wk, Wv, rkern, Wo, w16);

    // 1) merged projections
    k6<<<dim3(8, 16, 4), 256, 75776>>>(in16, w16, bk, bv, nullptr, proj,
        1024, 1024, 1024, 0);

    // 2) merged bias-dot tables
    dots_k<<<dim3(4096, 3), 256>>>(q16, k16, rh16, rwb, rrb, rsb, seg, rwk, rrt, ttd);

    // 3) fused content + pos + tt + mask -> sc
    score_k<<<dim3(8, 8, Bc * Nc), 256, 208896>>>(q16, k16, rh16, sc,
        rwk, rrt, ttd, ttm, clsm, amask);

    // 4) softmax -> bf16 probs
    softmax_k<<<Bc * Nc * Sc, 256>>>(sc, p16);

    // 5) PV
    k3<<<dim3(1, 8, Bc * Nc), 256, 59392>>>(p16, v16, nullptr, nullptr, nullptr, av16,
        1024, 1024, 1024, 0);

    // 6) output projection + bias
    k4<<<dim3(8, 16, 1), 256, 75776>>>(av16, w16 + 4LL * 1024 * 1024, bo, nullptr, ao, nullptr,
        1024, 1024, 1024, 1024);

    // 7) residual + LayerNorm
    ln_k<<<Bc * Sc, 256>>>(query, ao, gamma, beta, out);

    (void)in_sizes; (void)n_in; (void)out_size;
}

// round 6
// speedup vs baseline: 6.3679x; 1.2579x over previous
#include <cuda_runtime.h>
#include <cuda_bf16.h>
#include <math.h>
#include <stdint.h>

#define Bc 2
#define Sc 1024
#define Dc 1024
#define Nc 16
#define Hc 64
#define NHc 1024
#define Rc 2048
#define SCALE 0.125f
#define INFV 1000000.0f
#define EPSV 1e-9f
#define PSTR 137

typedef __nv_bfloat16 bf;

// ------------------------- scratch -------------------------
__device__ bf g_in16[4 * 2048 * 1024];
__device__ bf g_w16 [5 * 1024 * 1024];
__device__ bf g_proj[4 * 2048 * 1024];
__device__ bf g_av16[2048 * 1024];
__device__ float g_ao[2048 * 1024];
__device__ float g_rwk[32 * 1024];
__device__ float g_rrt[16 * 2048];
__device__ float g_ttd[2048 * 16 * 2];

// ------------------------- helpers -------------------------
__device__ __forceinline__ uint32_t cvta_s(const void* p){ return (uint32_t)__cvta_generic_to_shared(p); }
__device__ __forceinline__ void cp16(uint32_t d, const void* s){
    asm volatile("cp.async.cg.shared.global [%0], [%1], 16;" :: "r"(d), "l"(s));
}
__device__ __forceinline__ void ldm_x4(uint32_t* r, uint32_t a){
    asm volatile("ldmatrix.sync.aligned.m8n8.x4.shared.b16 {%0,%1,%2,%3}, [%4];"
                 : "=r"(r[0]), "=r"(r[1]), "=r"(r[2]), "=r"(r[3]) : "r"(a));
}
__device__ __forceinline__ void ldm_x2t(uint32_t* r, uint32_t a){
    asm volatile("ldmatrix.sync.aligned.m8n8.x2.trans.shared.b16 {%0,%1}, [%2];"
                 : "=r"(r[0]), "=r"(r[1]) : "r"(a));
}
__device__ __forceinline__ void ldm_x2(uint32_t* r, uint32_t a){
    asm volatile("ldmatrix.sync.aligned.m8n8.x2.shared.b16 {%0,%1}, [%2];"
                 : "=r"(r[0]), "=r"(r[1]) : "r"(a));
}
__device__ __forceinline__ void mma16816(float* d, const uint32_t* a, const uint32_t* b){
    asm volatile("mma.sync.aligned.m16n8k16.row.col.f32.bf16.bf16.f32 "
                 "{%0,%1,%2,%3}, {%4,%5,%6,%7}, {%8,%9}, {%0,%1,%2,%3};"
                 : "+f"(d[0]), "+f"(d[1]), "+f"(d[2]), "+f"(d[3])
                 : "r"(a[0]), "r"(a[1]), "r"(a[2]), "r"(a[3]), "r"(b[0]), "r"(b[1]));
}
__device__ __forceinline__ bf bfc(float x){ return __float2bfloat16(x); }
__device__ __forceinline__ uint32_t pack_bf(float x, float y){
    __nv_bfloat162 h; h.x = __float2bfloat16(x); h.y = __float2bfloat16(y);
    return *reinterpret_cast<uint32_t*>(&h);
}

// ------------------------- cast kernels -------------------------
__global__ void castA4_k(const float* __restrict__ i0, const float* __restrict__ i1,
                         const float* __restrict__ i2, const float* __restrict__ i3,
                         bf* __restrict__ out)
{
    const float* in = (blockIdx.y == 0) ? i0 : (blockIdx.y == 1) ? i1 : (blockIdx.y == 2) ? i2 : i3;
    long long i4 = ((long long)blockIdx.x * 256 + threadIdx.x) * 4;
    float4 v = *(const float4*)(in + i4);
    bf* o = out + (long long)blockIdx.y * 2048 * 1024 + i4;
    __nv_bfloat162 a, b;
    a.x = bfc(v.x); a.y = bfc(v.y); b.x = bfc(v.z); b.y = bfc(v.w);
    *(__nv_bfloat162*)(o)     = a;
    *(__nv_bfloat162*)(o + 2) = b;
}
__global__ void castW5_k(const float* __restrict__ i0, const float* __restrict__ i1,
                         const float* __restrict__ i2, const float* __restrict__ i3,
                         const float* __restrict__ i4p, bf* __restrict__ out)
{
    const float* in = (blockIdx.y == 0) ? i0 : (blockIdx.y == 1) ? i1 :
                      (blockIdx.y == 2) ? i2 : (blockIdx.y == 3) ? i3 : i4p;
    long long i4 = ((long long)blockIdx.x * 256 + threadIdx.x) * 4;
    float4 v = *(const float4*)(in + i4);
    bf* o = out + (long long)blockIdx.y * 1024 * 1024 + i4;
    __nv_bfloat162 a, b;
    a.x = bfc(v.x); a.y = bfc(v.y); b.x = bfc(v.z); b.y = bfc(v.w);
    *(__nv_bfloat162*)(o)     = a;
    *(__nv_bfloat162*)(o + 2) = b;
}

// ------------------------- generic bf16 GEMM (proj / outproj) ------------------
template<int BN, int NT_, int EPI>
__global__ __launch_bounds__(256, 2)
void tg(const bf* __restrict__ A, const bf* __restrict__ B,
        const float* __restrict__ bias, const float* __restrict__ bias2,
        float* __restrict__ Cf, bf* __restrict__ Cb,
        int K, int lda, int ldb, int ldc)
{
    constexpr int NS = 4;
    constexpr int ASZ = 128 * 40;
    constexpr int BSTR = BN + 8;
    constexpr int BSZ = 32 * BSTR;
    extern __shared__ __align__(16) bf dyn[];
    bf* Asm = dyn;
    bf* Bsm = dyn + NS * ASZ;

    const int m0 = blockIdx.y * 128;
    int n0 = blockIdx.x * BN;
    const int z = blockIdx.z;
    int zi = 0;
    if (EPI == 6){ zi = z; A += (long long)zi * 2048 * 1024; B += (long long)zi * 1024 * 1024; }

    const int t = threadIdx.x, lane = t & 31, warp = t >> 5, wm = warp >> 2, wn = warp & 3;

    float acc[4][NT_][4];
    #pragma unroll
    for (int a = 0; a < 4; ++a)
        #pragma unroll
        for (int b = 0; b < NT_; ++b)
            #pragma unroll
            for (int c = 0; c < 4; ++c) acc[a][b][c] = 0.f;

    auto loadA = [&](int s, int k0){
        #pragma unroll
        for (int q = 0; q < 2; ++q){
            int c = t * 2 + q, row = c >> 2, seg = c & 3;
            cp16(cvta_s(Asm + s * ASZ + row * 40 + seg * 8),
                 A + (long long)(m0 + row) * lda + k0 + seg * 8);
        }
    };
    auto loadB = [&](int s, int k0){
        constexpr int CPR = BN / 8;
        #pragma unroll
        for (int q = 0; q < (32 * CPR) / 256; ++q){
            int c = t * ((32 * CPR) / 256) + q, row = c / CPR, seg = c % CPR;
            cp16(cvta_s(Bsm + s * BSZ + row * BSTR + seg * 8),
                 B + (long long)(k0 + row) * ldb + n0 + seg * 8);
        }
    };

    const int KT = K / 32;
    loadA(0, 0); loadB(0, 0);
    asm volatile("cp.async.commit_group;");
    if (KT > 1){ loadA(1, 32); loadB(1, 32); }
    asm volatile("cp.async.commit_group;");
    if (KT > 2){ loadA(2, 64); loadB(2, 64); }
    asm volatile("cp.async.commit_group;");

    for (int kt = 0; kt < KT; ++kt){
        asm volatile("cp.async.wait_group 2;");
        __syncthreads();
        int kn = kt + 3;
        if (kn < KT){ loadA(kn & 3, kn * 32); loadB(kn & 3, kn * 32); }
        asm volatile("cp.async.commit_group;");

        const int s = kt & 3;
        const uint32_t aBase = cvta_s(Asm + s * ASZ) + ((wm * 64 + (lane & 15)) * 40) * 2;
        const uint32_t bBase = cvta_s(Bsm + s * BSZ);
        #pragma unroll
        for (int ks = 0; ks < 32; ks += 16){
            uint32_t af[4][4], bfrg[NT_][2];
            #pragma unroll
            for (int mt = 0; mt < 4; ++mt)
                ldm_x4(af[mt], aBase + (mt * 16 * 40 + ks + (lane >> 4) * 8) * 2);
            #pragma unroll
            for (int nt = 0; nt < NT_; ++nt)
                ldm_x2t(bfrg[nt], bBase + (((ks + (lane & 15)) * BSTR + wn * (BN / 4) + nt * 8)) * 2);
            #pragma unroll
            for (int mt = 0; mt < 4; ++mt)
                #pragma unroll
                for (int nt = 0; nt < NT_; ++nt) mma16816(acc[mt][nt], af[mt], bfrg[nt]);
        }
    }

    #pragma unroll
    for (int mt = 0; mt < 4; ++mt)
      #pragma unroll
      for (int r2 = 0; r2 < 2; ++r2){
        const int i = m0 + wm * 64 + mt * 16 + (lane >> 2) + r2 * 8;
        #pragma unroll
        for (int nt = 0; nt < NT_; ++nt)
          #pragma unroll
          for (int c2 = 0; c2 < 2; ++c2){
            const int j = n0 + wn * (BN / 4) + nt * 8 + ((lane & 3) << 1) + c2;
            float v = acc[mt][nt][r2 * 2 + c2];
            if (EPI == 6){
                if (zi == 0) v *= SCALE;
                else if (zi == 1) v += bias[j];
                else if (zi == 2) v += bias2[j];
                Cb[(long long)zi * 2048 * 1024 + (long long)i * 1024 + j] = bfc(v);
            } else { // EPI 4
                Cf[(long long)i * ldc + j] = v + bias[j];
            }
          }
      }
}

// ------------------------- fused flash attention kernel ----------------------
// grid (8 i-tiles, 32 bn). 256 thr, 8 warps, warp = 16 rows of the 128-row tile.
// Smem (bf16 units): qs[128*72] | ks[2][128*72] | vs[2][128*72] | rhs[256*72] | Pc fp32 [128*PSTR]
__global__ __launch_bounds__(256)
void fattn_k(const bf* __restrict__ q16, const bf* __restrict__ k16,
             const bf* __restrict__ v16, const bf* __restrict__ rh16,
             const float* __restrict__ rwk, const float* __restrict__ rrt,
             const float* __restrict__ ttd, const unsigned char* __restrict__ ttm,
             const float* __restrict__ clsm, const int* __restrict__ amask,
             bf* __restrict__ av16)
{
    extern __shared__ __align__(16) bf dyn[];
    bf* qs  = dyn;                 // 9216
    bf* ks  = dyn + 9216;          // 2 x 9216
    bf* vs  = dyn + 27648;         // 2 x 9216
    bf* rhs = dyn + 46080;         // 18432
    float* Pc = (float*)(dyn + 64512);   // 128 x PSTR fp32

    const int i0 = blockIdx.x * 128;
    const int z  = blockIdx.y, bb = z >> 4, nn = z & 15;
    const int t = threadIdx.x, lane = t & 31, w = t >> 5;
    const int l = lane & 15;
    float* Pw = Pc + w * 16 * PSTR;

    const bf* qg = q16 + ((long long)(bb * 1024 + i0)) * 1024 + nn * 64;

    auto loadQ = [&](){
        #pragma unroll
        for (int qq = 0; qq < 4; ++qq){
            int c = qq * 256 + t, row = c >> 3, seg = c & 7;
            cp16(cvta_s(qs + row * 72 + seg * 8), qg + (long long)row * 1024 + seg * 8);
        }
    };
    auto loadKV = [&](int buf, int j0){
        const bf* kg = k16 + ((long long)(bb * 1024 + j0)) * 1024 + nn * 64;
        const bf* vg = v16 + ((long long)(bb * 1024 + j0)) * 1024 + nn * 64;
        #pragma unroll
        for (int qq = 0; qq < 4; ++qq){
            int c = qq * 256 + t, row = c >> 3, seg = c & 7;
            cp16(cvta_s(ks + buf * 9216 + row * 72 + seg * 8), kg + (long long)row * 1024 + seg * 8);
        }
        #pragma unroll
        for (int qq = 0; qq < 4; ++qq){
            int c = qq * 256 + t, row = c >> 3, seg = c & 7;
            cp16(cvta_s(vs + buf * 9216 + row * 72 + seg * 8), vg + (long long)row * 1024 + seg * 8);
        }
    };
    auto loadRH = [&](int tb0){
        const bf* rg = rh16 + (long long)tb0 * 1024 + nn * 64;
        #pragma unroll
        for (int qq = 0; qq < 8; ++qq){
            int c = qq * 256 + t, row = c >> 3, seg = c & 7;
            cp16(cvta_s(rhs + row * 72 + seg * 8), rg + (long long)row * 1024 + seg * 8);
        }
    };

    loadQ(); loadKV(0, 0); loadRH(896 - i0);
    asm volatile("cp.async.commit_group;");
    asm volatile("cp.async.wait_group 0;");
    __syncthreads();

    const uint32_t aBase = cvta_s(qs) + ((w * 16 + l) * 72 + (lane >> 4) * 8) * 2;
    const uint32_t rBase = cvta_s(rhs);

    float accO[8][4];
    #pragma unroll
    for (int a = 0; a < 8; ++a){ accO[a][0] = 0.f; accO[a][1] = 0.f; accO[a][2] = 0.f; accO[a][3] = 0.f; }
    float m0 = -1e30f, m1 = -1e30f, l0 = 0.f, l1 = 0.f;

    const int rl0 = lane >> 2;
    const int iA = i0 + w * 16 + rl0, iB = iA + 8;
    const long long tba = ((long long)(bb * 1024 + iA) * 16 + nn) * 2;
    const long long tbb = ((long long)(bb * 1024 + iB) * 16 + nn) * 2;
    const float tdA0 = ttd[tba], tdA1 = ttd[tba + 1];
    const float tdB0 = ttd[tbb], tdB1 = ttd[tbb + 1];

    for (int jt = 0; jt < 8; ++jt){
        const int j0 = jt * 128;
        const int tb0 = 896 + j0 - i0;
        const int buf = jt & 1;

        if (jt > 0){ asm volatile("cp.async.wait_group 0;"); __syncthreads(); }

        // ---- pos mma (two 128-col halves) + warp-local diagonal scatter ----
        #pragma unroll
        for (int ph = 0; ph < 2; ++ph){
            float accP[16][4];
            #pragma unroll
            for (int a = 0; a < 16; ++a){ accP[a][0]=0.f; accP[a][1]=0.f; accP[a][2]=0.f; accP[a][3]=0.f; }
            #pragma unroll
            for (int ksx = 0; ksx < 64; ksx += 16){
                uint32_t af[4];
                ldm_x4(af, aBase + ksx * 2);
                #pragma unroll
                for (int nt = 0; nt < 16; ++nt){
                    uint32_t b2[2];
                    ldm_x2(b2, rBase + ((ph * 128 + nt * 8 + (l & 7)) * 72 + ksx + (l >> 3) * 8) * 2);
                    mma16816(accP[nt], af, b2);
                }
            }
            #pragma unroll
            for (int nt = 0; nt < 16; ++nt)
                #pragma unroll
                for (int c = 0; c < 4; ++c){
                    int rl = rl0 + ((c >> 1) << 3);
                    int di = w * 16 + rl;
                    int ct = ph * 128 + nt * 8 + ((lane & 3) << 1) + (c & 1);
                    int dj = ct - 128 + di;
                    if (dj >= 0 && dj < 128)
                        Pw[rl * PSTR + dj] = accP[nt][c] + rrt[nn * Rc + tb0 + ct];
                }
        }
        __syncwarp();

        // ---- content mma ----
        const uint32_t kBase = cvta_s(ks + buf * 9216);
        float accC[16][4];
        #pragma unroll
        for (int a = 0; a < 16; ++a){ accC[a][0]=0.f; accC[a][1]=0.f; accC[a][2]=0.f; accC[a][3]=0.f; }
        #pragma unroll
        for (int ksx = 0; ksx < 64; ksx += 16){
            uint32_t af[4];
            ldm_x4(af, aBase + ksx * 2);
            #pragma unroll
            for (int nt = 0; nt < 16; ++nt){
                uint32_t b2[2];
                ldm_x2(b2, kBase + ((nt * 8 + (l & 7)) * 72 + ksx + (l >> 3) * 8) * 2);
                mma16816(accC[nt], af, b2);
            }
        }

        // ---- assemble scores + online softmax ----
        float mtA = -1e30f, mtB = -1e30f;
        #pragma unroll
        for (int nt = 0; nt < 16; ++nt)
            #pragma unroll
            for (int c = 0; c < 4; ++c){
                int rl = rl0 + ((c >> 1) << 3);
                int i = (c < 2) ? iA : iB;
                int dj = nt * 8 + ((lane & 3) << 1) + (c & 1);
                int j = j0 + dj;
                float pval = Pw[rl * PSTR + dj];
                float tt = ttm[(long long)(bb * 1024 + i) * 1024 + j] ? ((c < 2) ? tdA1 : tdB1)
                                                                      : ((c < 2) ? tdA0 : tdB0);
                float cl = clsm[(long long)i * 1024 + j];
                float v = accC[nt][c] + rwk[(long long)z * 1024 + j] + (pval + tt) * cl
                          - INFV * (1.0f - (float)amask[bb * 1024 + j]);
                accC[nt][c] = v;
                if (c < 2) mtA = fmaxf(mtA, v); else mtB = fmaxf(mtB, v);
            }
        mtA = fmaxf(mtA, __shfl_xor_sync(0xffffffffu, mtA, 1));
        mtA = fmaxf(mtA, __shfl_xor_sync(0xffffffffu, mtA, 2));
        mtB = fmaxf(mtB, __shfl_xor_sync(0xffffffffu, mtB, 1));
        mtB = fmaxf(mtB, __shfl_xor_sync(0xffffffffu, mtB, 2));
        float mnA = fmaxf(m0, mtA), mnB = fmaxf(m1, mtB);
        float corA = __expf(m0 - mnA), corB = __expf(m1 - mnB);
        float sA = 0.f, sB = 0.f;
        #pragma unroll
        for (int nt = 0; nt < 16; ++nt)
            #pragma unroll
            for (int c = 0; c < 4; ++c){
                float e = __expf(accC[nt][c] - ((c < 2) ? mnA : mnB));
                accC[nt][c] = e;
                if (c < 2) sA += e; else sB += e;
            }
        sA += __shfl_xor_sync(0xffffffffu, sA, 1);
        sA += __shfl_xor_sync(0xffffffffu, sA, 2);
        sB += __shfl_xor_sync(0xffffffffu, sB, 1);
        sB += __shfl_xor_sync(0xffffffffu, sB, 2);
        l0 = l0 * corA + sA; l1 = l1 * corB + sB; m0 = mnA; m1 = mnB;
        #pragma unroll
        for (int a = 0; a < 8; ++a){
            accO[a][0] *= corA; accO[a][1] *= corA; accO[a][2] *= corB; accO[a][3] *= corB;
        }

        __syncthreads();
        if (jt < 7){
            loadKV(buf ^ 1, j0 + 128);
            loadRH(tb0 + 128);
            asm volatile("cp.async.commit_group;");
        }

        // ---- PV mma: accO += P @ V ----
        const uint32_t vBase = cvta_s(vs + buf * 9216);
        #pragma unroll
        for (int kb = 0; kb < 8; ++kb){
            uint32_t pf[4];
            pf[0] = pack_bf(accC[2 * kb][0],     accC[2 * kb][1]);
            pf[1] = pack_bf(accC[2 * kb][2],     accC[2 * kb][3]);
            pf[2] = pack_bf(accC[2 * kb + 1][0], accC[2 * kb + 1][1]);
            pf[3] = pack_bf(accC[2 * kb + 1][2], accC[2 * kb + 1][3]);
            #pragma unroll
            for (int nt = 0; nt < 8; ++nt){
                uint32_t bv2[2];
                ldm_x2t(bv2, vBase + ((kb * 16 + l) * 72 + nt * 8) * 2);
                mma16816(accO[nt], pf, bv2);
            }
        }
    }

    // ---- finalize ----
    float invA = 1.0f / l0, invB = 1.0f / l1;
    int rA = bb * 1024 + iA, rB = bb * 1024 + iB;
    #pragma unroll
    for (int nt = 0; nt < 8; ++nt){
        int col = nn * 64 + nt * 8 + ((lane & 3) << 1);
        __nv_bfloat162 p0, p1;
        p0.x = bfc(accO[nt][0] * invA); p0.y = bfc(accO[nt][1] * invA);
        p1.x = bfc(accO[nt][2] * invB); p1.y = bfc(accO[nt][3] * invB);
        *(__nv_bfloat162*)(av16 + (long long)rA * 1024 + col) = p0;
        *(__nv_bfloat162*)(av16 + (long long)rB * 1024 + col) = p1;
    }
}

// ------------------------- merged dot kernels -------------------------
__global__ void dots_k(const bf* __restrict__ q16, const bf* __restrict__ k16,
                       const bf* __restrict__ rh16,
                       const float* __restrict__ rwb, const float* __restrict__ rrb,
                       const float* __restrict__ rsb, const float* __restrict__ seg,
                       float* __restrict__ rwk, float* __restrict__ rrt, float* __restrict__ ttd)
{
    int gw = (blockIdx.x * blockDim.x + threadIdx.x) >> 5;
    int lane = threadIdx.x & 31;
    if (blockIdx.y == 0){
        int zz = gw >> 10, j = gw & (Sc - 1);
        int b = zz >> 4, n = zz & 15;
        const bf* kp = k16 + ((long long)(b * 1024 + j)) * 1024 + n * 64;
        float d = 0.f;
        #pragma unroll
        for (int h = lane; h < Hc; h += 32) d += rwb[n * Hc + h] * __bfloat162float(kp[h]);
        #pragma unroll
        for (int o = 16; o; o >>= 1) d += __shfl_down_sync(0xffffffffu, d, o);
        if (lane == 0) rwk[gw] = d * SCALE;
    } else if (blockIdx.y == 1){
        int n = gw >> 11, tt2 = gw & (Rc - 1);
        const bf* rp = rh16 + (long long)tt2 * 1024 + n * 64;
        float d = 0.f;
        #pragma unroll
        for (int h = lane; h < Hc; h += 32) d += rrb[n * Hc + h] * __bfloat162float(rp[h]);
        #pragma unroll
        for (int o = 16; o; o >>= 1) d += __shfl_down_sync(0xffffffffu, d, o);
        if (lane == 0) rrt[gw] = d * SCALE;
    } else {
        int n = gw & 15;
        long long bi = gw >> 4;
        const bf* qp = q16 + bi * 1024 + n * 64;
        float d0 = 0.f, d1 = 0.f, s0 = 0.f, s1 = 0.f;
        #pragma unroll
        for (int h = lane; h < Hc; h += 32){
            float e0 = seg[n * Hc + h], e1 = seg[Nc * Hc + n * Hc + h];
            float qv = __bfloat162float(qp[h]), rv = rsb[n * Hc + h];
            d0 += qv * e0; d1 += qv * e1; s0 += rv * e0; s1 += rv * e1;
        }
        #pragma unroll
        for (int o = 16; o; o >>= 1){
            d0 += __shfl_down_sync(0xffffffffu, d0, o);
            d1 += __shfl_down_sync(0xffffffffu, d1, o);
            s0 += __shfl_down_sync(0xffffffffu, s0, o);
            s1 += __shfl_down_sync(0xffffffffu, s1, o);
        }
        if (lane == 0){ ttd[2 * gw] = d0 + SCALE * s0; ttd[2 * gw + 1] = d1 + SCALE * s1; }
    }
}

// ------------------------- residual + LayerNorm -------------------------
__global__ void ln_k(const float* __restrict__ query, const float* __restrict__ ao,
                     const float* __restrict__ gamma, const float* __restrict__ beta,
                     float* __restrict__ out){
    __shared__ float red[256];
    long long base = (long long)blockIdx.x * Dc;
    int t = threadIdx.x;
    float x[4]; float s = 0.f;
    #pragma unroll
    for (int u = 0; u < 4; ++u){ x[u] = query[base + t + u * 256] + ao[base + t + u * 256]; s += x[u]; }
    red[t] = s; __syncthreads();
    #pragma unroll
    for (int o = 128; o; o >>= 1){ if (t < o) red[t] += red[t + o]; __syncthreads(); }
    float mu = red[0] * (1.0f / Dc); __syncthreads();
    float s2 = 0.f;
    #pragma unroll
    for (int u = 0; u < 4; ++u){ float d = x[u] - mu; s2 += d * d; }
    red[t] = s2; __syncthreads();
    #pragma unroll
    for (int o = 128; o; o >>= 1){ if (t < o) red[t] += red[t + o]; __syncthreads(); }
    float inv = rsqrtf(red[0] * (1.0f / Dc) + EPSV);
    #pragma unroll
    for (int u = 0; u < 4; ++u){
        int c = t + u * 256;
        out[base + c] = (x[u] - mu) * inv * gamma[c] + beta[c];
    }
}

// ------------------------- driver -------------------------
extern "C" void kernel_launch(void* const* d_in, const int* in_sizes, int n_in,
                              void* d_out, int out_size)
{
    const float* query = (const float*)d_in[0];
    const float* key   = (const float*)d_in[1];
    const float* value = (const float*)d_in[2];
    const float* r     = (const float*)d_in[3];
    const float* clsm  = (const float*)d_in[4];
    const float* Wq    = (const float*)d_in[5];
    const float* Wk    = (const float*)d_in[6];
    const float* bk    = (const float*)d_in[7];
    const float* Wv    = (const float*)d_in[8];
    const float* bv    = (const float*)d_in[9];
    const float* Wo    = (const float*)d_in[10];
    const float* bo    = (const float*)d_in[11];
    const float* rwb   = (const float*)d_in[12];
    const float* rrb   = (const float*)d_in[13];
    const float* rkern = (const float*)d_in[14];
    const float* rsb   = (const float*)d_in[15];
    const float* seg   = (const float*)d_in[16];
    const float* gamma = (const float*)d_in[17];
    const float* beta  = (const float*)d_in[18];
    const unsigned char* ttm = (const unsigned char*)d_in[19];
    const int*   amask = (const int*)d_in[20];
    float* out = (float*)d_out;

    bf *in16, *w16, *proj, *av16;
    float *ao, *rwk, *rrt, *ttd;
    cudaGetSymbolAddress((void**)&in16, g_in16);
    cudaGetSymbolAddress((void**)&w16,  g_w16);
    cudaGetSymbolAddress((void**)&proj, g_proj);
    cudaGetSymbolAddress((void**)&av16, g_av16);
    cudaGetSymbolAddress((void**)&ao,   g_ao);
    cudaGetSymbolAddress((void**)&rwk,  g_rwk);
    cudaGetSymbolAddress((void**)&rrt,  g_rrt);
    cudaGetSymbolAddress((void**)&ttd,  g_ttd);

    bf* q16  = proj;
    bf* k16  = proj + 1LL * 2048 * 1024;
    bf* v16  = proj + 2LL * 2048 * 1024;
    bf* rh16 = proj + 3LL * 2048 * 1024;

    auto k6 = tg<128, 4, 6>;
    auto k4 = tg<128, 4, 4>;
    cudaFuncSetAttribute(k6, cudaFuncAttributeMaxDynamicSharedMemorySize, 75776);
    cudaFuncSetAttribute(k4, cudaFuncAttributeMaxDynamicSharedMemorySize, 75776);
    cudaFuncSetAttribute(fattn_k, cudaFuncAttributeMaxDynamicSharedMemorySize, 199168);

    // 0) casts
    castA4_k<<<dim3(2048, 4), 256>>>(query, key, value, r, in16);
    castW5_k<<<dim3(1024, 5), 256>>>(Wq, Wk, Wv, rkern, Wo, w16);

    // 1) merged projections
    k6<<<dim3(8, 16, 4), 256, 75776>>>(in16, w16, bk, bv, nullptr, proj,
        1024, 1024, 1024, 0);

    // 2) merged bias-dot tables
    dots_k<<<dim3(4096, 3), 256>>>(q16, k16, rh16, rwb, rrb, rsb, seg, rwk, rrt, ttd);

    // 3) fused scores + softmax + PV (flash attention with relative pos)
    fattn_k<<<dim3(8, 32), 256, 199168>>>(q16, k16, v16, rh16,
        rwk, rrt, ttd, ttm, clsm, amask, av16);

    // 4) output projection + bias
    k4<<<dim3(8, 16, 1), 256, 75776>>>(av16, w16 + 4LL * 1024 * 1024, bo, nullptr, ao, nullptr,
        1024, 1024, 1024, 1024);

    // 5) residual + LayerNorm
    ln_k<<<Bc * Sc, 256>>>(query, ao, gamma, beta, out);

    (void)in_sizes; (void)n_in; (void)out_size;
}

// round 7
// speedup vs baseline: 6.9299x; 1.0883x over previous
#include <cuda_runtime.h>
#include <cuda_bf16.h>
#include <math.h>
#include <stdint.h>

#define Bc 2
#define Sc 1024
#define Dc 1024
#define Nc 16
#define Hc 64
#define NHc 1024
#define Rc 2048
#define SCALE 0.125f
#define INFV 1000000.0f
#define EPSV 1e-9f
#define PSTR 137

typedef __nv_bfloat16 bf;

// ------------------------- scratch -------------------------
__device__ bf g_in16[4 * 2048 * 1024];
__device__ bf g_w16 [5 * 1024 * 1024];
__device__ bf g_proj[4 * 2048 * 1024];
__device__ bf g_av16[2048 * 1024];
__device__ float g_ao[2048 * 1024];
__device__ float g_rwk[32 * 1024];
__device__ float g_rrt[16 * 2048];
__device__ float g_ttd[2048 * 16 * 2];

// ------------------------- helpers -------------------------
__device__ __forceinline__ uint32_t cvta_s(const void* p){ return (uint32_t)__cvta_generic_to_shared(p); }
__device__ __forceinline__ void cp16(uint32_t d, const void* s){
    asm volatile("cp.async.cg.shared.global [%0], [%1], 16;" :: "r"(d), "l"(s));
}
__device__ __forceinline__ void ldm_x4(uint32_t* r, uint32_t a){
    asm volatile("ldmatrix.sync.aligned.m8n8.x4.shared.b16 {%0,%1,%2,%3}, [%4];"
                 : "=r"(r[0]), "=r"(r[1]), "=r"(r[2]), "=r"(r[3]) : "r"(a));
}
__device__ __forceinline__ void ldm_x2t(uint32_t* r, uint32_t a){
    asm volatile("ldmatrix.sync.aligned.m8n8.x2.trans.shared.b16 {%0,%1}, [%2];"
                 : "=r"(r[0]), "=r"(r[1]) : "r"(a));
}
__device__ __forceinline__ void ldm_x2(uint32_t* r, uint32_t a){
    asm volatile("ldmatrix.sync.aligned.m8n8.x2.shared.b16 {%0,%1}, [%2];"
                 : "=r"(r[0]), "=r"(r[1]) : "r"(a));
}
__device__ __forceinline__ void mma16816(float* d, const uint32_t* a, const uint32_t* b){
    asm volatile("mma.sync.aligned.m16n8k16.row.col.f32.bf16.bf16.f32 "
                 "{%0,%1,%2,%3}, {%4,%5,%6,%7}, {%8,%9}, {%0,%1,%2,%3};"
                 : "+f"(d[0]), "+f"(d[1]), "+f"(d[2]), "+f"(d[3])
                 : "r"(a[0]), "r"(a[1]), "r"(a[2]), "r"(a[3]), "r"(b[0]), "r"(b[1]));
}
__device__ __forceinline__ bf bfc(float x){ return __float2bfloat16(x); }
__device__ __forceinline__ uint32_t pack_bf(float x, float y){
    __nv_bfloat162 h; h.x = __float2bfloat16(x); h.y = __float2bfloat16(y);
    return *reinterpret_cast<uint32_t*>(&h);
}

// ------------------------- merged cast kernel -------------------------
// grid.y 0..3: A inputs (2048x1024, 2048 blocks); 4..8: weights (1024x1024, 1024 blocks)
__global__ void castAll_k(const float* __restrict__ a0, const float* __restrict__ a1,
                          const float* __restrict__ a2, const float* __restrict__ a3,
                          const float* __restrict__ w0, const float* __restrict__ w1,
                          const float* __restrict__ w2, const float* __restrict__ w3,
                          const float* __restrict__ w4,
                          bf* __restrict__ outA, bf* __restrict__ outW)
{
    int y = blockIdx.y;
    const float* in; bf* o;
    if (y < 4){
        in = (y == 0) ? a0 : (y == 1) ? a1 : (y == 2) ? a2 : a3;
        o  = outA + (long long)y * 2048 * 1024;
    } else {
        if (blockIdx.x >= 1024) return;
        int yw = y - 4;
        in = (yw == 0) ? w0 : (yw == 1) ? w1 : (yw == 2) ? w2 : (yw == 3) ? w3 : w4;
        o  = outW + (long long)yw * 1024 * 1024;
    }
    long long i4 = ((long long)blockIdx.x * 256 + threadIdx.x) * 4;
    float4 v = *(const float4*)(in + i4);
    __nv_bfloat162 p, q;
    p.x = bfc(v.x); p.y = bfc(v.y); q.x = bfc(v.z); q.y = bfc(v.w);
    *(__nv_bfloat162*)(o + i4)     = p;
    *(__nv_bfloat162*)(o + i4 + 2) = q;
}

// ------------------------- generic bf16 GEMM (proj / outproj) ------------------
template<int BN, int NT_, int EPI>
__global__ __launch_bounds__(256, 2)
void tg(const bf* __restrict__ A, const bf* __restrict__ B,
        const float* __restrict__ bias, const float* __restrict__ bias2,
        float* __restrict__ Cf, bf* __restrict__ Cb,
        int K, int lda, int ldb, int ldc)
{
    constexpr int NS = 4;
    constexpr int ASZ = 128 * 40;
    constexpr int BSTR = BN + 8;
    constexpr int BSZ = 32 * BSTR;
    extern __shared__ __align__(16) bf dyn[];
    bf* Asm = dyn;
    bf* Bsm = dyn + NS * ASZ;

    const int m0 = blockIdx.y * 128;
    int n0 = blockIdx.x * BN;
    const int z = blockIdx.z;
    int zi = 0;
    if (EPI == 6){ zi = z; A += (long long)zi * 2048 * 1024; B += (long long)zi * 1024 * 1024; }

    const int t = threadIdx.x, lane = t & 31, warp = t >> 5, wm = warp >> 2, wn = warp & 3;

    float acc[4][NT_][4];
    #pragma unroll
    for (int a = 0; a < 4; ++a)
        #pragma unroll
        for (int b = 0; b < NT_; ++b)
            #pragma unroll
            for (int c = 0; c < 4; ++c) acc[a][b][c] = 0.f;

    auto loadA = [&](int s, int k0){
        #pragma unroll
        for (int q = 0; q < 2; ++q){
            int c = t * 2 + q, row = c >> 2, seg = c & 3;
            cp16(cvta_s(Asm + s * ASZ + row * 40 + seg * 8),
                 A + (long long)(m0 + row) * lda + k0 + seg * 8);
        }
    };
    auto loadB = [&](int s, int k0){
        constexpr int CPR = BN / 8;
        #pragma unroll
        for (int q = 0; q < (32 * CPR) / 256; ++q){
            int c = t * ((32 * CPR) / 256) + q, row = c / CPR, seg = c % CPR;
            cp16(cvta_s(Bsm + s * BSZ + row * BSTR + seg * 8),
                 B + (long long)(k0 + row) * ldb + n0 + seg * 8);
        }
    };

    const int KT = K / 32;
    loadA(0, 0); loadB(0, 0);
    asm volatile("cp.async.commit_group;");
    if (KT > 1){ loadA(1, 32); loadB(1, 32); }
    asm volatile("cp.async.commit_group;");
    if (KT > 2){ loadA(2, 64); loadB(2, 64); }
    asm volatile("cp.async.commit_group;");

    for (int kt = 0; kt < KT; ++kt){
        asm volatile("cp.async.wait_group 2;");
        __syncthreads();
        int kn = kt + 3;
        if (kn < KT){ loadA(kn & 3, kn * 32); loadB(kn & 3, kn * 32); }
        asm volatile("cp.async.commit_group;");

        const int s = kt & 3;
        const uint32_t aBase = cvta_s(Asm + s * ASZ) + ((wm * 64 + (lane & 15)) * 40) * 2;
        const uint32_t bBase = cvta_s(Bsm + s * BSZ);
        #pragma unroll
        for (int ks = 0; ks < 32; ks += 16){
            uint32_t af[4][4], bfrg[NT_][2];
            #pragma unroll
            for (int mt = 0; mt < 4; ++mt)
                ldm_x4(af[mt], aBase + (mt * 16 * 40 + ks + (lane >> 4) * 8) * 2);
            #pragma unroll
            for (int nt = 0; nt < NT_; ++nt)
                ldm_x2t(bfrg[nt], bBase + (((ks + (lane & 15)) * BSTR + wn * (BN / 4) + nt * 8)) * 2);
            #pragma unroll
            for (int mt = 0; mt < 4; ++mt)
                #pragma unroll
                for (int nt = 0; nt < NT_; ++nt) mma16816(acc[mt][nt], af[mt], bfrg[nt]);
        }
    }

    #pragma unroll
    for (int mt = 0; mt < 4; ++mt)
      #pragma unroll
      for (int r2 = 0; r2 < 2; ++r2){
        const int i = m0 + wm * 64 + mt * 16 + (lane >> 2) + r2 * 8;
        #pragma unroll
        for (int nt = 0; nt < NT_; ++nt)
          #pragma unroll
          for (int c2 = 0; c2 < 2; ++c2){
            const int j = n0 + wn * (BN / 4) + nt * 8 + ((lane & 3) << 1) + c2;
            float v = acc[mt][nt][r2 * 2 + c2];
            if (EPI == 6){
                if (zi == 0) v *= SCALE;
                else if (zi == 1) v += bias[j];
                else if (zi == 2) v += bias2[j];
                Cb[(long long)zi * 2048 * 1024 + (long long)i * 1024 + j] = bfc(v);
            } else { // EPI 4
                Cf[(long long)i * ldc + j] = v + bias[j];
            }
          }
      }
}

// ------------------------- fused flash attention kernel ----------------------
// grid (8 i-tiles, 32 bn). 256 thr, 8 warps, warp = 16 rows.
// Pos mma restricted to the per-warp diagonal band: tiles 14-2w .. 31-2w (18 of 32).
__global__ __launch_bounds__(256)
void fattn_k(const bf* __restrict__ q16, const bf* __restrict__ k16,
             const bf* __restrict__ v16, const bf* __restrict__ rh16,
             const float* __restrict__ rwkm, const float* __restrict__ rrt,
             const float* __restrict__ ttd, const unsigned char* __restrict__ ttm,
             const float* __restrict__ clsm, bf* __restrict__ av16)
{
    extern __shared__ __align__(16) bf dyn[];
    bf* qs  = dyn;                 // 9216
    bf* ks  = dyn + 9216;          // 2 x 9216
    bf* vs  = dyn + 27648;         // 2 x 9216
    bf* rhs = dyn + 46080;         // 18432
    float* Pc = (float*)(dyn + 64512);   // 128 x PSTR fp32

    const int i0 = blockIdx.x * 128;
    const int z  = blockIdx.y, bb = z >> 4, nn = z & 15;
    const int t = threadIdx.x, lane = t & 31, w = t >> 5;
    const int l = lane & 15;
    float* Pw = Pc + w * 16 * PSTR;

    const bf* qg = q16 + ((long long)(bb * 1024 + i0)) * 1024 + nn * 64;

    auto loadQ = [&](){
        #pragma unroll
        for (int qq = 0; qq < 4; ++qq){
            int c = qq * 256 + t, row = c >> 3, seg = c & 7;
            cp16(cvta_s(qs + row * 72 + seg * 8), qg + (long long)row * 1024 + seg * 8);
        }
    };
    auto loadKV = [&](int buf, int j0){
        const bf* kg = k16 + ((long long)(bb * 1024 + j0)) * 1024 + nn * 64;
        const bf* vg = v16 + ((long long)(bb * 1024 + j0)) * 1024 + nn * 64;
        #pragma unroll
        for (int qq = 0; qq < 4; ++qq){
            int c = qq * 256 + t, row = c >> 3, seg = c & 7;
            cp16(cvta_s(ks + buf * 9216 + row * 72 + seg * 8), kg + (long long)row * 1024 + seg * 8);
        }
        #pragma unroll
        for (int qq = 0; qq < 4; ++qq){
            int c = qq * 256 + t, row = c >> 3, seg = c & 7;
            cp16(cvta_s(vs + buf * 9216 + row * 72 + seg * 8), vg + (long long)row * 1024 + seg * 8);
        }
    };
    auto loadRH = [&](int tb0){
        const bf* rg = rh16 + (long long)tb0 * 1024 + nn * 64;
        #pragma unroll
        for (int qq = 0; qq < 8; ++qq){
            int c = qq * 256 + t, row = c >> 3, seg = c & 7;
            cp16(cvta_s(rhs + row * 72 + seg * 8), rg + (long long)row * 1024 + seg * 8);
        }
    };

    loadQ(); loadKV(0, 0); loadRH(896 - i0);
    asm volatile("cp.async.commit_group;");
    asm volatile("cp.async.wait_group 0;");
    __syncthreads();

    const uint32_t aBase = cvta_s(qs) + ((w * 16 + l) * 72 + (lane >> 4) * 8) * 2;
    const uint32_t rBase = cvta_s(rhs);

    // hoisted Q fragments (invariant across all j-steps and phases)
    uint32_t afq[4][4];
    #pragma unroll
    for (int s = 0; s < 4; ++s) ldm_x4(afq[s], aBase + (s * 16) * 2);

    float accO[8][4];
    #pragma unroll
    for (int a = 0; a < 8; ++a){ accO[a][0] = 0.f; accO[a][1] = 0.f; accO[a][2] = 0.f; accO[a][3] = 0.f; }
    float m0 = -1e30f, m1 = -1e30f, l0 = 0.f, l1 = 0.f;

    const int rl0 = lane >> 2;
    const int iA = i0 + w * 16 + rl0, iB = iA + 8;
    const long long tba = ((long long)(bb * 1024 + iA) * 16 + nn) * 2;
    const long long tbb = ((long long)(bb * 1024 + iB) * 16 + nn) * 2;
    const float tdA0 = ttd[tba], tdA1 = ttd[tba + 1];
    const float tdB0 = ttd[tbb], tdB1 = ttd[tbb + 1];
    const int nt0 = 14 - 2 * w;          // first band tile for this warp

    for (int jt = 0; jt < 8; ++jt){
        const int j0 = jt * 128;
        const int tb0 = 896 + j0 - i0;
        const int buf = jt & 1;
        const float* rrtp = rrt + nn * Rc + tb0;

        if (jt > 0){ asm volatile("cp.async.wait_group 0;"); __syncthreads(); }

        // ---- band-limited pos mma (18 tiles in two groups of 9) ----
        #pragma unroll
        for (int g = 0; g < 2; ++g){
            float accP[9][4];
            #pragma unroll
            for (int a = 0; a < 9; ++a){ accP[a][0]=0.f; accP[a][1]=0.f; accP[a][2]=0.f; accP[a][3]=0.f; }
            #pragma unroll
            for (int s = 0; s < 4; ++s){
                #pragma unroll
                for (int u = 0; u < 9; ++u){
                    int nt = nt0 + g * 9 + u;
                    uint32_t b2[2];
                    ldm_x2(b2, rBase + ((nt * 8 + (l & 7)) * 72 + s * 16 + (l >> 3) * 8) * 2);
                    mma16816(accP[u], afq[s], b2);
                }
            }
            #pragma unroll
            for (int u = 0; u < 9; ++u){
                int nt = nt0 + g * 9 + u;
                #pragma unroll
                for (int c = 0; c < 4; ++c){
                    int rl = rl0 + ((c >> 1) << 3);
                    int di = w * 16 + rl;
                    int ct = nt * 8 + ((lane & 3) << 1) + (c & 1);
                    int dj = ct - 128 + di;
                    if (dj >= 0 && dj < 128)
                        Pw[rl * PSTR + dj] = accP[u][c] + rrtp[ct];
                }
            }
        }
        __syncwarp();

        // ---- content mma ----
        const uint32_t kBase = cvta_s(ks + buf * 9216);
        float accC[16][4];
        #pragma unroll
        for (int a = 0; a < 16; ++a){ accC[a][0]=0.f; accC[a][1]=0.f; accC[a][2]=0.f; accC[a][3]=0.f; }
        #pragma unroll
        for (int s = 0; s < 4; ++s){
            #pragma unroll
            for (int nt = 0; nt < 16; ++nt){
                uint32_t b2[2];
                ldm_x2(b2, kBase + ((nt * 8 + (l & 7)) * 72 + s * 16 + (l >> 3) * 8) * 2);
                mma16816(accC[nt], afq[s], b2);
            }
        }

        // ---- assemble scores + online softmax ----
        float mtA = -1e30f, mtB = -1e30f;
        #pragma unroll
        for (int nt = 0; nt < 16; ++nt)
            #pragma unroll
            for (int c = 0; c < 4; ++c){
                int rl = rl0 + ((c >> 1) << 3);
                int i = (c < 2) ? iA : iB;
                int dj = nt * 8 + ((lane & 3) << 1) + (c & 1);
                int j = j0 + dj;
                float pval = Pw[rl * PSTR + dj];
                float tt = ttm[(long long)(bb * 1024 + i) * 1024 + j] ? ((c < 2) ? tdA1 : tdB1)
                                                                      : ((c < 2) ? tdA0 : tdB0);
                float cl = clsm[(long long)i * 1024 + j];
                float v = accC[nt][c] + rwkm[(long long)z * 1024 + j] + (pval + tt) * cl;
                accC[nt][c] = v;
                if (c < 2) mtA = fmaxf(mtA, v); else mtB = fmaxf(mtB, v);
            }
        mtA = fmaxf(mtA, __shfl_xor_sync(0xffffffffu, mtA, 1));
        mtA = fmaxf(mtA, __shfl_xor_sync(0xffffffffu, mtA, 2));
        mtB = fmaxf(mtB, __shfl_xor_sync(0xffffffffu, mtB, 1));
        mtB = fmaxf(mtB, __shfl_xor_sync(0xffffffffu, mtB, 2));
        float mnA = fmaxf(m0, mtA), mnB = fmaxf(m1, mtB);
        float corA = __expf(m0 - mnA), corB = __expf(m1 - mnB);
        float sA = 0.f, sB = 0.f;
        #pragma unroll
        for (int nt = 0; nt < 16; ++nt)
            #pragma unroll
            for (int c = 0; c < 4; ++c){
                float e = __expf(accC[nt][c] - ((c < 2) ? mnA : mnB));
                accC[nt][c] = e;
                if (c < 2) sA += e; else sB += e;
            }
        sA += __shfl_xor_sync(0xffffffffu, sA, 1);
        sA += __shfl_xor_sync(0xffffffffu, sA, 2);
        sB += __shfl_xor_sync(0xffffffffu, sB, 1);
        sB += __shfl_xor_sync(0xffffffffu, sB, 2);
        l0 = l0 * corA + sA; l1 = l1 * corB + sB; m0 = mnA; m1 = mnB;
        #pragma unroll
        for (int a = 0; a < 8; ++a){
            accO[a][0] *= corA; accO[a][1] *= corA; accO[a][2] *= corB; accO[a][3] *= corB;
        }

        __syncthreads();
        if (jt < 7){
            loadKV(buf ^ 1, j0 + 128);
            loadRH(tb0 + 128);
            asm volatile("cp.async.commit_group;");
        }

        // ---- PV mma: accO += P @ V ----
        const uint32_t vBase = cvta_s(vs + buf * 9216);
        #pragma unroll
        for (int kb = 0; kb < 8; ++kb){
            uint32_t pf[4];
            pf[0] = pack_bf(accC[2 * kb][0],     accC[2 * kb][1]);
            pf[1] = pack_bf(accC[2 * kb][2],     accC[2 * kb][3]);
            pf[2] = pack_bf(accC[2 * kb + 1][0], accC[2 * kb + 1][1]);
            pf[3] = pack_bf(accC[2 * kb + 1][2], accC[2 * kb + 1][3]);
            #pragma unroll
            for (int nt = 0; nt < 8; ++nt){
                uint32_t bv2[2];
                ldm_x2t(bv2, vBase + ((kb * 16 + l) * 72 + nt * 8) * 2);
                mma16816(accO[nt], pf, bv2);
            }
        }
    }

    // ---- finalize ----
    float invA = 1.0f / l0, invB = 1.0f / l1;
    int rA = bb * 1024 + iA, rB = bb * 1024 + iB;
    #pragma unroll
    for (int nt = 0; nt < 8; ++nt){
        int col = nn * 64 + nt * 8 + ((lane & 3) << 1);
        __nv_bfloat162 p0, p1;
        p0.x = bfc(accO[nt][0] * invA); p0.y = bfc(accO[nt][1] * invA);
        p1.x = bfc(accO[nt][2] * invB); p1.y = bfc(accO[nt][3] * invB);
        *(__nv_bfloat162*)(av16 + (long long)rA * 1024 + col) = p0;
        *(__nv_bfloat162*)(av16 + (long long)rB * 1024 + col) = p1;
    }
}

// ------------------------- merged dot kernels -------------------------
// pass 0 also folds the attention mask: rwkm = rwb.k*SCALE - INF*(1-mask[j])
__global__ void dots_k(const bf* __restrict__ q16, const bf* __restrict__ k16,
                       const bf* __restrict__ rh16,
                       const float* __restrict__ rwb, const float* __restrict__ rrb,
                       const float* __restrict__ rsb, const float* __restrict__ seg,
                       const int* __restrict__ amask,
                       float* __restrict__ rwkm, float* __restrict__ rrt, float* __restrict__ ttd)
{
    int gw = (blockIdx.x * blockDim.x + threadIdx.x) >> 5;
    int lane = threadIdx.x & 31;
    if (blockIdx.y == 0){
        int zz = gw >> 10, j = gw & (Sc - 1);
        int b = zz >> 4, n = zz & 15;
        const bf* kp = k16 + ((long long)(b * 1024 + j)) * 1024 + n * 64;
        float d = 0.f;
        #pragma unroll
        for (int h = lane; h < Hc; h += 32) d += rwb[n * Hc + h] * __bfloat162float(kp[h]);
        #pragma unroll
        for (int o = 16; o; o >>= 1) d += __shfl_down_sync(0xffffffffu, d, o);
        if (lane == 0) rwkm[gw] = d * SCALE - INFV * (1.0f - (float)amask[b * Sc + j]);
    } else if (blockIdx.y == 1){
        int n = gw >> 11, tt2 = gw & (Rc - 1);
        const bf* rp = rh16 + (long long)tt2 * 1024 + n * 64;
        float d = 0.f;
        #pragma unroll
        for (int h = lane; h < Hc; h += 32) d += rrb[n * Hc + h] * __bfloat162float(rp[h]);
        #pragma unroll
        for (int o = 16; o; o >>= 1) d += __shfl_down_sync(0xffffffffu, d, o);
        if (lane == 0) rrt[gw] = d * SCALE;
    } else {
        int n = gw & 15;
        long long bi = gw >> 4;
        const bf* qp = q16 + bi * 1024 + n * 64;
        float d0 = 0.f, d1 = 0.f, s0 = 0.f, s1 = 0.f;
        #pragma unroll
        for (int h = lane; h < Hc; h += 32){
            float e0 = seg[n * Hc + h], e1 = seg[Nc * Hc + n * Hc + h];
            float qv = __bfloat162float(qp[h]), rv = rsb[n * Hc + h];
            d0 += qv * e0; d1 += qv * e1; s0 += rv * e0; s1 += rv * e1;
        }
        #pragma unroll
        for (int o = 16; o; o >>= 1){
            d0 += __shfl_down_sync(0xffffffffu, d0, o);
            d1 += __shfl_down_sync(0xffffffffu, d1, o);
            s0 += __shfl_down_sync(0xffffffffu, s0, o);
            s1 += __shfl_down_sync(0xffffffffu, s1, o);
        }
        if (lane == 0){ ttd[2 * gw] = d0 + SCALE * s0; ttd[2 * gw + 1] = d1 + SCALE * s1; }
    }
}

// ------------------------- residual + LayerNorm -------------------------
__global__ void ln_k(const float* __restrict__ query, const float* __restrict__ ao,
                     const float* __restrict__ gamma, const float* __restrict__ beta,
                     float* __restrict__ out){
    __shared__ float red[256];
    long long base = (long long)blockIdx.x * Dc;
    int t = threadIdx.x;
    float x[4]; float s = 0.f;
    #pragma unroll
    for (int u = 0; u < 4; ++u){ x[u] = query[base + t + u * 256] + ao[base + t + u * 256]; s += x[u]; }
    red[t] = s; __syncthreads();
    #pragma unroll
    for (int o = 128; o; o >>= 1){ if (t < o) red[t] += red[t + o]; __syncthreads(); }
    float mu = red[0] * (1.0f / Dc); __syncthreads();
    float s2 = 0.f;
    #pragma unroll
    for (int u = 0; u < 4; ++u){ float d = x[u] - mu; s2 += d * d; }
    red[t] = s2; __syncthreads();
    #pragma unroll
    for (int o = 128; o; o >>= 1){ if (t < o) red[t] += red[t + o]; __syncthreads(); }
    float inv = rsqrtf(red[0] * (1.0f / Dc) + EPSV);
    #pragma unroll
    for (int u = 0; u < 4; ++u){
        int c = t + u * 256;
        out[base + c] = (x[u] - mu) * inv * gamma[c] + beta[c];
    }
}

// ------------------------- driver -------------------------
extern "C" void kernel_launch(void* const* d_in, const int* in_sizes, int n_in,
                              void* d_out, int out_size)
{
    const float* query = (const float*)d_in[0];
    const float* key   = (const float*)d_in[1];
    const float* value = (const float*)d_in[2];
    const float* r     = (const float*)d_in[3];
    const float* clsm  = (const float*)d_in[4];
    const float* Wq    = (const float*)d_in[5];
    const float* Wk    = (const float*)d_in[6];
    const float* bk    = (const float*)d_in[7];
    const float* Wv    = (const float*)d_in[8];
    const float* bv    = (const float*)d_in[9];
    const float* Wo    = (const float*)d_in[10];
    const float* bo    = (const float*)d_in[11];
    const float* rwb   = (const float*)d_in[12];
    const float* rrb   = (const float*)d_in[13];
    const float* rkern = (const float*)d_in[14];
    const float* rsb   = (const float*)d_in[15];
    const float* seg   = (const float*)d_in[16];
    const float* gamma = (const float*)d_in[17];
    const float* beta  = (const float*)d_in[18];
    const unsigned char* ttm = (const unsigned char*)d_in[19];
    const int*   amask = (const int*)d_in[20];
    float* out = (float*)d_out;

    bf *in16, *w16, *proj, *av16;
    float *ao, *rwk, *rrt, *ttd;
    cudaGetSymbolAddress((void**)&in16, g_in16);
    cudaGetSymbolAddress((void**)&w16,  g_w16);
    cudaGetSymbolAddress((void**)&proj, g_proj);
    cudaGetSymbolAddress((void**)&av16, g_av16);
    cudaGetSymbolAddress((void**)&ao,   g_ao);
    cudaGetSymbolAddress((void**)&rwk,  g_rwk);
    cudaGetSymbolAddress((void**)&rrt,  g_rrt);
    cudaGetSymbolAddress((void**)&ttd,  g_ttd);

    bf* q16  = proj;
    bf* k16  = proj + 1LL * 2048 * 1024;
    bf* v16  = proj + 2LL * 2048 * 1024;
    bf* rh16 = proj + 3LL * 2048 * 1024;

    auto k6 = tg<128, 4, 6>;
    auto k4 = tg<128, 4, 4>;
    cudaFuncSetAttribute(k6, cudaFuncAttributeMaxDynamicSharedMemorySize, 75776);
    cudaFuncSetAttribute(k4, cudaFuncAttributeMaxDynamicSharedMemorySize, 75776);
    cudaFuncSetAttribute(fattn_k, cudaFuncAttributeMaxDynamicSharedMemorySize, 199168);

    // 0) casts (merged)
    castAll_k<<<dim3(2048, 9), 256>>>(query, key, value, r, Wq, Wk, Wv, rkern, Wo, in16, w16);

    // 1) merged projections
    k6<<<dim3(8, 16, 4), 256, 75776>>>(in16, w16, bk, bv, nullptr, proj,
        1024, 1024, 1024, 0);

    // 2) merged bias-dot tables (mask folded into rwk)
    dots_k<<<dim3(4096, 3), 256>>>(q16, k16, rh16, rwb, rrb, rsb, seg, amask, rwk, rrt, ttd);

    // 3) fused scores + softmax + PV
    fattn_k<<<dim3(8, 32), 256, 199168>>>(q16, k16, v16, rh16,
        rwk, rrt, ttd, ttm, clsm, av16);

    // 4) output projection + bias
    k4<<<dim3(8, 16, 1), 256, 75776>>>(av16, w16 + 4LL * 1024 * 1024, bo, nullptr, ao, nullptr,
        1024, 1024, 1024, 1024);

    // 5) residual + LayerNorm
    ln_k<<<Bc * Sc, 256>>>(query, ao, gamma, beta, out);

    (void)in_sizes; (void)n_in; (void)out_size;
}

// round 8
// speedup vs baseline: 7.8260x; 1.1293x over previous
#include <cuda_runtime.h>
#include <cuda_bf16.h>
#include <math.h>
#include <stdint.h>

#define Bc 2
#define Sc 1024
#define Dc 1024
#define Nc 16
#define Hc 64
#define NHc 1024
#define Rc 2048
#define SCALE 0.125f
#define INFV 1000000.0f
#define EPSV 1e-9f
#define PSTR 137

typedef __nv_bfloat16 bf;

// ------------------------- scratch -------------------------
__device__ bf g_in16[4 * 2048 * 1024];
__device__ bf g_w16 [5 * 1024 * 1024];
__device__ bf g_proj[4 * 2048 * 1024];
__device__ bf g_av16[2048 * 1024];
__device__ float g_ao[2048 * 1024];
__device__ float g_rwk[32 * 1024];
__device__ float g_rrt[16 * 2048];
__device__ float g_ttd[2048 * 16 * 2];

// ------------------------- helpers -------------------------
__device__ __forceinline__ uint32_t cvta_s(const void* p){ return (uint32_t)__cvta_generic_to_shared(p); }
__device__ __forceinline__ void cp16(uint32_t d, const void* s){
    asm volatile("cp.async.cg.shared.global [%0], [%1], 16;" :: "r"(d), "l"(s));
}
__device__ __forceinline__ void ldm_x4(uint32_t* r, uint32_t a){
    asm volatile("ldmatrix.sync.aligned.m8n8.x4.shared.b16 {%0,%1,%2,%3}, [%4];"
                 : "=r"(r[0]), "=r"(r[1]), "=r"(r[2]), "=r"(r[3]) : "r"(a));
}
__device__ __forceinline__ void ldm_x4t(uint32_t* r, uint32_t a){
    asm volatile("ldmatrix.sync.aligned.m8n8.x4.trans.shared.b16 {%0,%1,%2,%3}, [%4];"
                 : "=r"(r[0]), "=r"(r[1]), "=r"(r[2]), "=r"(r[3]) : "r"(a));
}
__device__ __forceinline__ void ldm_x2t(uint32_t* r, uint32_t a){
    asm volatile("ldmatrix.sync.aligned.m8n8.x2.trans.shared.b16 {%0,%1}, [%2];"
                 : "=r"(r[0]), "=r"(r[1]) : "r"(a));
}
__device__ __forceinline__ void mma16816(float* d, const uint32_t* a, const uint32_t* b){
    asm volatile("mma.sync.aligned.m16n8k16.row.col.f32.bf16.bf16.f32 "
                 "{%0,%1,%2,%3}, {%4,%5,%6,%7}, {%8,%9}, {%0,%1,%2,%3};"
                 : "+f"(d[0]), "+f"(d[1]), "+f"(d[2]), "+f"(d[3])
                 : "r"(a[0]), "r"(a[1]), "r"(a[2]), "r"(a[3]), "r"(b[0]), "r"(b[1]));
}
__device__ __forceinline__ bf bfc(float x){ return __float2bfloat16(x); }
__device__ __forceinline__ uint32_t pack_bf(float x, float y){
    __nv_bfloat162 h; h.x = __float2bfloat16(x); h.y = __float2bfloat16(y);
    return *reinterpret_cast<uint32_t*>(&h);
}

// ------------------------- merged cast kernel -------------------------
__global__ void castAll_k(const float* __restrict__ a0, const float* __restrict__ a1,
                          const float* __restrict__ a2, const float* __restrict__ a3,
                          const float* __restrict__ w0, const float* __restrict__ w1,
                          const float* __restrict__ w2, const float* __restrict__ w3,
                          const float* __restrict__ w4,
                          bf* __restrict__ outA, bf* __restrict__ outW)
{
    int y = blockIdx.y;
    const float* in; bf* o;
    if (y < 4){
        in = (y == 0) ? a0 : (y == 1) ? a1 : (y == 2) ? a2 : a3;
        o  = outA + (long long)y * 2048 * 1024;
    } else {
        if (blockIdx.x >= 1024) return;
        int yw = y - 4;
        in = (yw == 0) ? w0 : (yw == 1) ? w1 : (yw == 2) ? w2 : (yw == 3) ? w3 : w4;
        o  = outW + (long long)yw * 1024 * 1024;
    }
    long long i4 = ((long long)blockIdx.x * 256 + threadIdx.x) * 4;
    float4 v = *(const float4*)(in + i4);
    __nv_bfloat162 p, q;
    p.x = bfc(v.x); p.y = bfc(v.y); q.x = bfc(v.z); q.y = bfc(v.w);
    *(__nv_bfloat162*)(o + i4)     = p;
    *(__nv_bfloat162*)(o + i4 + 2) = q;
}

// ------------------------- generic bf16 GEMM (proj / outproj) ------------------
template<int BN, int NT_, int EPI>
__global__ __launch_bounds__(256, 2)
void tg(const bf* __restrict__ A, const bf* __restrict__ B,
        const float* __restrict__ bias, const float* __restrict__ bias2,
        float* __restrict__ Cf, bf* __restrict__ Cb,
        int K, int lda, int ldb, int ldc)
{
    constexpr int NS = 4;
    constexpr int ASZ = 128 * 40;
    constexpr int BSTR = BN + 8;
    constexpr int BSZ = 32 * BSTR;
    extern __shared__ __align__(16) bf dyn[];
    bf* Asm = dyn;
    bf* Bsm = dyn + NS * ASZ;

    const int m0 = blockIdx.y * 128;
    int n0 = blockIdx.x * BN;
    const int z = blockIdx.z;
    int zi = 0;
    if (EPI == 6){ zi = z; A += (long long)zi * 2048 * 1024; B += (long long)zi * 1024 * 1024; }

    const int t = threadIdx.x, lane = t & 31, warp = t >> 5, wm = warp >> 2, wn = warp & 3;

    float acc[4][NT_][4];
    #pragma unroll
    for (int a = 0; a < 4; ++a)
        #pragma unroll
        for (int b = 0; b < NT_; ++b)
            #pragma unroll
            for (int c = 0; c < 4; ++c) acc[a][b][c] = 0.f;

    auto loadA = [&](int s, int k0){
        #pragma unroll
        for (int q = 0; q < 2; ++q){
            int c = t * 2 + q, row = c >> 2, seg = c & 3;
            cp16(cvta_s(Asm + s * ASZ + row * 40 + seg * 8),
                 A + (long long)(m0 + row) * lda + k0 + seg * 8);
        }
    };
    auto loadB = [&](int s, int k0){
        constexpr int CPR = BN / 8;
        #pragma unroll
        for (int q = 0; q < (32 * CPR) / 256; ++q){
            int c = t * ((32 * CPR) / 256) + q, row = c / CPR, seg = c % CPR;
            cp16(cvta_s(Bsm + s * BSZ + row * BSTR + seg * 8),
                 B + (long long)(k0 + row) * ldb + n0 + seg * 8);
        }
    };

    const int KT = K / 32;
    loadA(0, 0); loadB(0, 0);
    asm volatile("cp.async.commit_group;");
    if (KT > 1){ loadA(1, 32); loadB(1, 32); }
    asm volatile("cp.async.commit_group;");
    if (KT > 2){ loadA(2, 64); loadB(2, 64); }
    asm volatile("cp.async.commit_group;");

    for (int kt = 0; kt < KT; ++kt){
        asm volatile("cp.async.wait_group 2;");
        __syncthreads();
        int kn = kt + 3;
        if (kn < KT){ loadA(kn & 3, kn * 32); loadB(kn & 3, kn * 32); }
        asm volatile("cp.async.commit_group;");

        const int s = kt & 3;
        const uint32_t aBase = cvta_s(Asm + s * ASZ) + ((wm * 64 + (lane & 15)) * 40) * 2;
        const uint32_t bBase = cvta_s(Bsm + s * BSZ);
        #pragma unroll
        for (int ks = 0; ks < 32; ks += 16){
            uint32_t af[4][4], bfrg[NT_][2];
            #pragma unroll
            for (int mt = 0; mt < 4; ++mt)
                ldm_x4(af[mt], aBase + (mt * 16 * 40 + ks + (lane >> 4) * 8) * 2);
            #pragma unroll
            for (int nt = 0; nt < NT_; ++nt)
                ldm_x2t(bfrg[nt], bBase + (((ks + (lane & 15)) * BSTR + wn * (BN / 4) + nt * 8)) * 2);
            #pragma unroll
            for (int mt = 0; mt < 4; ++mt)
                #pragma unroll
                for (int nt = 0; nt < NT_; ++nt) mma16816(acc[mt][nt], af[mt], bfrg[nt]);
        }
    }

    #pragma unroll
    for (int mt = 0; mt < 4; ++mt)
      #pragma unroll
      for (int r2 = 0; r2 < 2; ++r2){
        const int i = m0 + wm * 64 + mt * 16 + (lane >> 2) + r2 * 8;
        #pragma unroll
        for (int nt = 0; nt < NT_; ++nt)
          #pragma unroll
          for (int c2 = 0; c2 < 2; ++c2){
            const int j = n0 + wn * (BN / 4) + nt * 8 + ((lane & 3) << 1) + c2;
            float v = acc[mt][nt][r2 * 2 + c2];
            if (EPI == 6){
                if (zi == 0) v *= SCALE;
                else if (zi == 1) v += bias[j];
                else if (zi == 2) v += bias2[j];
                Cb[(long long)zi * 2048 * 1024 + (long long)i * 1024 + j] = bfc(v);
            } else { // EPI 4
                Cf[(long long)i * ldc + j] = v + bias[j];
            }
          }
      }
}

// ------------------------- fused flash attention kernel ----------------------
// grid (8 i-tiles, 32 bn). 256 thr, 8 warps, warp = 16 rows.
// No-max softmax (scores bounded); exp+pack immediately; x4 ldmatrix everywhere.
__global__ __launch_bounds__(256)
void fattn_k(const bf* __restrict__ q16, const bf* __restrict__ k16,
             const bf* __restrict__ v16, const bf* __restrict__ rh16,
             const float* __restrict__ rwkm, const float* __restrict__ rrt,
             const float* __restrict__ ttd, const unsigned char* __restrict__ ttm,
             const float* __restrict__ clsm, bf* __restrict__ av16)
{
    extern __shared__ __align__(16) bf dyn[];
    bf* qs  = dyn;                 // 9216
    bf* ks  = dyn + 9216;          // 2 x 9216
    bf* vs  = dyn + 27648;         // 2 x 9216
    bf* rhs = dyn + 46080;         // 18432
    float* Pc = (float*)(dyn + 64512);   // 128 x PSTR fp32

    const int i0 = blockIdx.x * 128;
    const int z  = blockIdx.y, bb = z >> 4, nn = z & 15;
    const int t = threadIdx.x, lane = t & 31, w = t >> 5;
    float* Pw = Pc + w * 16 * PSTR;

    const bf* qg = q16 + ((long long)(bb * 1024 + i0)) * 1024 + nn * 64;

    auto loadQ = [&](){
        #pragma unroll
        for (int qq = 0; qq < 4; ++qq){
            int c = qq * 256 + t, row = c >> 3, seg = c & 7;
            cp16(cvta_s(qs + row * 72 + seg * 8), qg + (long long)row * 1024 + seg * 8);
        }
    };
    auto loadKV = [&](int buf, int j0){
        const bf* kg = k16 + ((long long)(bb * 1024 + j0)) * 1024 + nn * 64;
        const bf* vg = v16 + ((long long)(bb * 1024 + j0)) * 1024 + nn * 64;
        #pragma unroll
        for (int qq = 0; qq < 4; ++qq){
            int c = qq * 256 + t, row = c >> 3, seg = c & 7;
            cp16(cvta_s(ks + buf * 9216 + row * 72 + seg * 8), kg + (long long)row * 1024 + seg * 8);
        }
        #pragma unroll
        for (int qq = 0; qq < 4; ++qq){
            int c = qq * 256 + t, row = c >> 3, seg = c & 7;
            cp16(cvta_s(vs + buf * 9216 + row * 72 + seg * 8), vg + (long long)row * 1024 + seg * 8);
        }
    };
    auto loadRH = [&](int tb0){
        const bf* rg = rh16 + (long long)tb0 * 1024 + nn * 64;
        #pragma unroll
        for (int qq = 0; qq < 8; ++qq){
            int c = qq * 256 + t, row = c >> 3, seg = c & 7;
            cp16(cvta_s(rhs + row * 72 + seg * 8), rg + (long long)row * 1024 + seg * 8);
        }
    };

    loadQ(); loadKV(0, 0); loadRH(896 - i0);
    asm volatile("cp.async.commit_group;");
    asm volatile("cp.async.wait_group 0;");
    __syncthreads();

    const uint32_t aBase = cvta_s(qs) + ((w * 16 + (lane & 15)) * 72 + (lane >> 4) * 8) * 2;
    const uint32_t rBase = cvta_s(rhs);

    // hoisted Q fragments
    uint32_t afq[4][4];
    #pragma unroll
    for (int s = 0; s < 4; ++s) ldm_x4(afq[s], aBase + (s * 16) * 2);

    float accO[8][4];
    #pragma unroll
    for (int a = 0; a < 8; ++a){ accO[a][0] = 0.f; accO[a][1] = 0.f; accO[a][2] = 0.f; accO[a][3] = 0.f; }
    float lsumA = 0.f, lsumB = 0.f;

    const int rl0 = lane >> 2;
    const int iA = i0 + w * 16 + rl0, iB = iA + 8;
    const long long tba = ((long long)(bb * 1024 + iA) * 16 + nn) * 2;
    const long long tbb = ((long long)(bb * 1024 + iB) * 16 + nn) * 2;
    const float tdA0 = ttd[tba], tdA1 = ttd[tba + 1];
    const float tdB0 = ttd[tbb], tdB1 = ttd[tbb + 1];
    const int nt0 = 14 - 2 * w;
    // x4 B-fragment lane address components
    const int bnOff = (lane & 7) + ((lane >> 4) << 3);   // n-row within 16-row pair
    const int bkOff = ((lane >> 3) & 1) << 3;            // k offset 0/8

    for (int jt = 0; jt < 8; ++jt){
        const int j0 = jt * 128;
        const int tb0 = 896 + j0 - i0;
        const int buf = jt & 1;
        const float* rrtp = rrt + nn * Rc + tb0;

        if (jt > 0){ asm volatile("cp.async.wait_group 0;"); __syncthreads(); }

        // ---- band-limited pos mma: 18 tiles = 3 groups x (3 x4 loads -> 6 tiles) ----
        #pragma unroll
        for (int g = 0; g < 3; ++g){
            float accP[6][4];
            #pragma unroll
            for (int a = 0; a < 6; ++a){ accP[a][0]=0.f; accP[a][1]=0.f; accP[a][2]=0.f; accP[a][3]=0.f; }
            #pragma unroll
            for (int s = 0; s < 4; ++s){
                #pragma unroll
                for (int u = 0; u < 3; ++u){
                    int ntp = nt0 + g * 6 + u * 2;
                    uint32_t b4[4];
                    ldm_x4(b4, rBase + ((ntp * 8 + bnOff) * 72 + s * 16 + bkOff) * 2);
                    mma16816(accP[2 * u],     afq[s], b4);
                    mma16816(accP[2 * u + 1], afq[s], b4 + 2);
                }
            }
            #pragma unroll
            for (int u = 0; u < 6; ++u){
                int nt = nt0 + g * 6 + u;
                #pragma unroll
                for (int c = 0; c < 4; ++c){
                    int rl = rl0 + ((c >> 1) << 3);
                    int di = w * 16 + rl;
                    int ct = nt * 8 + ((lane & 3) << 1) + (c & 1);
                    int dj = ct - 128 + di;
                    if (dj >= 0 && dj < 128)
                        Pw[rl * PSTR + dj] = accP[u][c] + rrtp[ct];
                }
            }
        }
        __syncwarp();

        // ---- content mma (x4 loads, two tiles per load) ----
        const uint32_t kBase = cvta_s(ks + buf * 9216);
        float accC[16][4];
        #pragma unroll
        for (int a = 0; a < 16; ++a){ accC[a][0]=0.f; accC[a][1]=0.f; accC[a][2]=0.f; accC[a][3]=0.f; }
        #pragma unroll
        for (int s = 0; s < 4; ++s){
            #pragma unroll
            for (int np = 0; np < 8; ++np){
                uint32_t b4[4];
                ldm_x4(b4, kBase + ((np * 16 + bnOff) * 72 + s * 16 + bkOff) * 2);
                mma16816(accC[2 * np],     afq[s], b4);
                mma16816(accC[2 * np + 1], afq[s], b4 + 2);
            }
        }

        __syncthreads();   // all warps done with rhs + ks[buf] mma reads
        if (jt < 7){
            loadKV(buf ^ 1, j0 + 128);
            loadRH(tb0 + 128);
            asm volatile("cp.async.commit_group;");
        }

        // ---- assemble scores, exp, pack (no max pass) ----
        uint32_t pkA[16], pkB[16];
        const float* rwp = rwkm + (long long)z * 1024 + j0;
        #pragma unroll
        for (int nt = 0; nt < 16; ++nt){
            const int djp = nt * 8 + ((lane & 3) << 1);
            const int jp = j0 + djp;
            float2 rw = *(const float2*)(rwp + djp);
            // row A
            {
                float2 cl = *(const float2*)(clsm + (long long)iA * 1024 + jp);
                uchar2 tm = *(const uchar2*)(ttm + (long long)(bb * 1024 + iA) * 1024 + jp);
                float p0 = Pw[rl0 * PSTR + djp], p1 = Pw[rl0 * PSTR + djp + 1];
                float e0 = __expf(accC[nt][0] + rw.x + (p0 + (tm.x ? tdA1 : tdA0)) * cl.x);
                float e1 = __expf(accC[nt][1] + rw.y + (p1 + (tm.y ? tdA1 : tdA0)) * cl.y);
                lsumA += e0 + e1;
                pkA[nt] = pack_bf(e0, e1);
            }
            // row B
            {
                float2 cl = *(const float2*)(clsm + (long long)iB * 1024 + jp);
                uchar2 tm = *(const uchar2*)(ttm + (long long)(bb * 1024 + iB) * 1024 + jp);
                float p0 = Pw[(rl0 + 8) * PSTR + djp], p1 = Pw[(rl0 + 8) * PSTR + djp + 1];
                float e0 = __expf(accC[nt][2] + rw.x + (p0 + (tm.x ? tdB1 : tdB0)) * cl.x);
                float e1 = __expf(accC[nt][3] + rw.y + (p1 + (tm.y ? tdB1 : tdB0)) * cl.y);
                lsumB += e0 + e1;
                pkB[nt] = pack_bf(e0, e1);
            }
        }

        // ---- PV mma: accO += P @ V (x4.trans loads) ----
        const uint32_t vBase = cvta_s(vs + buf * 9216);
        #pragma unroll
        for (int kb = 0; kb < 8; ++kb){
            uint32_t pf[4];
            pf[0] = pkA[2 * kb];     pf[1] = pkB[2 * kb];
            pf[2] = pkA[2 * kb + 1]; pf[3] = pkB[2 * kb + 1];
            #pragma unroll
            for (int np = 0; np < 4; ++np){
                uint32_t b4[4];
                ldm_x4t(b4, vBase + ((kb * 16 + (lane & 15)) * 72 + np * 16 + (lane >> 4) * 8) * 2);
                mma16816(accO[2 * np],     pf, b4);
                mma16816(accO[2 * np + 1], pf, b4 + 2);
            }
        }
    }

    // ---- finalize: quad-reduce row sums, normalize, store ----
    lsumA += __shfl_xor_sync(0xffffffffu, lsumA, 1);
    lsumA += __shfl_xor_sync(0xffffffffu, lsumA, 2);
    lsumB += __shfl_xor_sync(0xffffffffu, lsumB, 1);
    lsumB += __shfl_xor_sync(0xffffffffu, lsumB, 2);
    float invA = 1.0f / lsumA, invB = 1.0f / lsumB;
    int rA = bb * 1024 + iA, rB = bb * 1024 + iB;
    #pragma unroll
    for (int nt = 0; nt < 8; ++nt){
        int col = nn * 64 + nt * 8 + ((lane & 3) << 1);
        __nv_bfloat162 p0, p1;
        p0.x = bfc(accO[nt][0] * invA); p0.y = bfc(accO[nt][1] * invA);
        p1.x = bfc(accO[nt][2] * invB); p1.y = bfc(accO[nt][3] * invB);
        *(__nv_bfloat162*)(av16 + (long long)rA * 1024 + col) = p0;
        *(__nv_bfloat162*)(av16 + (long long)rB * 1024 + col) = p1;
    }
}

// ------------------------- merged dot kernels -------------------------
__global__ void dots_k(const bf* __restrict__ q16, const bf* __restrict__ k16,
                       const bf* __restrict__ rh16,
                       const float* __restrict__ rwb, const float* __restrict__ rrb,
                       const float* __restrict__ rsb, const float* __restrict__ seg,
                       const int* __restrict__ amask,
                       float* __restrict__ rwkm, float* __restrict__ rrt, float* __restrict__ ttd)
{
    int gw = (blockIdx.x * blockDim.x + threadIdx.x) >> 5;
    int lane = threadIdx.x & 31;
    if (blockIdx.y == 0){
        int zz = gw >> 10, j = gw & (Sc - 1);
        int b = zz >> 4, n = zz & 15;
        const bf* kp = k16 + ((long long)(b * 1024 + j)) * 1024 + n * 64;
        float d = 0.f;
        #pragma unroll
        for (int h = lane; h < Hc; h += 32) d += rwb[n * Hc + h] * __bfloat162float(kp[h]);
        #pragma unroll
        for (int o = 16; o; o >>= 1) d += __shfl_down_sync(0xffffffffu, d, o);
        if (lane == 0) rwkm[gw] = d * SCALE - INFV * (1.0f - (float)amask[b * Sc + j]);
    } else if (blockIdx.y == 1){
        int n = gw >> 11, tt2 = gw & (Rc - 1);
        const bf* rp = rh16 + (long long)tt2 * 1024 + n * 64;
        float d = 0.f;
        #pragma unroll
        for (int h = lane; h < Hc; h += 32) d += rrb[n * Hc + h] * __bfloat162float(rp[h]);
        #pragma unroll
        for (int o = 16; o; o >>= 1) d += __shfl_down_sync(0xffffffffu, d, o);
        if (lane == 0) rrt[gw] = d * SCALE;
    } else {
        int n = gw & 15;
        long long bi = gw >> 4;
        const bf* qp = q16 + bi * 1024 + n * 64;
        float d0 = 0.f, d1 = 0.f, s0 = 0.f, s1 = 0.f;
        #pragma unroll
        for (int h = lane; h < Hc; h += 32){
            float e0 = seg[n * Hc + h], e1 = seg[Nc * Hc + n * Hc + h];
            float qv = __bfloat162float(qp[h]), rv = rsb[n * Hc + h];
            d0 += qv * e0; d1 += qv * e1; s0 += rv * e0; s1 += rv * e1;
        }
        #pragma unroll
        for (int o = 16; o; o >>= 1){
            d0 += __shfl_down_sync(0xffffffffu, d0, o);
            d1 += __shfl_down_sync(0xffffffffu, d1, o);
            s0 += __shfl_down_sync(0xffffffffu, s0, o);
            s1 += __shfl_down_sync(0xffffffffu, s1, o);
        }
        if (lane == 0){ ttd[2 * gw] = d0 + SCALE * s0; ttd[2 * gw + 1] = d1 + SCALE * s1; }
    }
}

// ------------------------- residual + LayerNorm -------------------------
__global__ void ln_k(const float* __restrict__ query, const float* __restrict__ ao,
                     const float* __restrict__ gamma, const float* __restrict__ beta,
                     float* __restrict__ out){
    __shared__ float red[256];
    long long base = (long long)blockIdx.x * Dc;
    int t = threadIdx.x;
    float x[4]; float s = 0.f;
    #pragma unroll
    for (int u = 0; u < 4; ++u){ x[u] = query[base + t + u * 256] + ao[base + t + u * 256]; s += x[u]; }
    red[t] = s; __syncthreads();
    #pragma unroll
    for (int o = 128; o; o >>= 1){ if (t < o) red[t] += red[t + o]; __syncthreads(); }
    float mu = red[0] * (1.0f / Dc); __syncthreads();
    float s2 = 0.f;
    #pragma unroll
    for (int u = 0; u < 4; ++u){ float d = x[u] - mu; s2 += d * d; }
    red[t] = s2; __syncthreads();
    #pragma unroll
    for (int o = 128; o; o >>= 1){ if (t < o) red[t] += red[t + o]; __syncthreads(); }
    float inv = rsqrtf(red[0] * (1.0f / Dc) + EPSV);
    #pragma unroll
    for (int u = 0; u < 4; ++u){
        int c = t + u * 256;
        out[base + c] = (x[u] - mu) * inv * gamma[c] + beta[c];
    }
}

// ------------------------- driver -------------------------
extern "C" void kernel_launch(void* const* d_in, const int* in_sizes, int n_in,
                              void* d_out, int out_size)
{
    const float* query = (const float*)d_in[0];
    const float* key   = (const float*)d_in[1];
    const float* value = (const float*)d_in[2];
    const float* r     = (const float*)d_in[3];
    const float* clsm  = (const float*)d_in[4];
    const float* Wq    = (const float*)d_in[5];
    const float* Wk    = (const float*)d_in[6];
    const float* bk    = (const float*)d_in[7];
    const float* Wv    = (const float*)d_in[8];
    const float* bv    = (const float*)d_in[9];
    const float* Wo    = (const float*)d_in[10];
    const float* bo    = (const float*)d_in[11];
    const float* rwb   = (const float*)d_in[12];
    const float* rrb   = (const float*)d_in[13];
    const float* rkern = (const float*)d_in[14];
    const float* rsb   = (const float*)d_in[15];
    const float* seg   = (const float*)d_in[16];
    const float* gamma = (const float*)d_in[17];
    const float* beta  = (const float*)d_in[18];
    const unsigned char* ttm = (const unsigned char*)d_in[19];
    const int*   amask = (const int*)d_in[20];
    float* out = (float*)d_out;

    bf *in16, *w16, *proj, *av16;
    float *ao, *rwk, *rrt, *ttd;
    cudaGetSymbolAddress((void**)&in16, g_in16);
    cudaGetSymbolAddress((void**)&w16,  g_w16);
    cudaGetSymbolAddress((void**)&proj, g_proj);
    cudaGetSymbolAddress((void**)&av16, g_av16);
    cudaGetSymbolAddress((void**)&ao,   g_ao);
    cudaGetSymbolAddress((void**)&rwk,  g_rwk);
    cudaGetSymbolAddress((void**)&rrt,  g_rrt);
    cudaGetSymbolAddress((void**)&ttd,  g_ttd);

    bf* q16  = proj;
    bf* k16  = proj + 1LL * 2048 * 1024;
    bf* v16  = proj + 2LL * 2048 * 1024;
    bf* rh16 = proj + 3LL * 2048 * 1024;

    auto k6 = tg<128, 4, 6>;
    auto k4 = tg<128, 4, 4>;
    cudaFuncSetAttribute(k6, cudaFuncAttributeMaxDynamicSharedMemorySize, 75776);
    cudaFuncSetAttribute(k4, cudaFuncAttributeMaxDynamicSharedMemorySize, 75776);
    cudaFuncSetAttribute(fattn_k, cudaFuncAttributeMaxDynamicSharedMemorySize, 199168);

    // 0) casts (merged)
    castAll_k<<<dim3(2048, 9), 256>>>(query, key, value, r, Wq, Wk, Wv, rkern, Wo, in16, w16);

    // 1) merged projections
    k6<<<dim3(8, 16, 4), 256, 75776>>>(in16, w16, bk, bv, nullptr, proj,
        1024, 1024, 1024, 0);

    // 2) merged bias-dot tables (mask folded into rwk)
    dots_k<<<dim3(4096, 3), 256>>>(q16, k16, rh16, rwb, rrb, rsb, seg, amask, rwk, rrt, ttd);

    // 3) fused scores + softmax + PV
    fattn_k<<<dim3(8, 32), 256, 199168>>>(q16, k16, v16, rh16,
        rwk, rrt, ttd, ttm, clsm, av16);

    // 4) output projection + bias
    k4<<<dim3(8, 16, 1), 256, 75776>>>(av16, w16 + 4LL * 1024 * 1024, bo, nullptr, ao, nullptr,
        1024, 1024, 1024, 1024);

    // 5) residual + LayerNorm
    ln_k<<<Bc * Sc, 256>>>(query, ao, gamma, beta, out);

    (void)in_sizes; (void)n_in; (void)out_size;
}